// round 1
// baseline (speedup 1.0000x reference)
#include <cuda_runtime.h>

#define DIM   768
#define NH    12
#define HD    64
#define GH    48           // grid H = W
#define HW    2304         // 48*48
#define RANK  32
#define QK_SCALE 0.125f    // 64^-0.5
#define FACT_S 1.0f

// ---------------- device scratch (no allocations allowed) ----------------
__device__ float g_A1[DIM * RANK];        // FacTu @ q_FacTs
__device__ float g_A2[DIM * RANK];        // FacTu @ v_FacTs
__device__ float g_Weff[DIM * 3 * DIM];   // folded qkv weight
__device__ float g_qkv[HW * 3 * DIM];     // qkv activations [2304, 2304]
__device__ float g_relh[NH * HW * GH];    // rel bias tables
__device__ float g_relw[NH * HW * GH];
__device__ float g_opre[HW * DIM];        // attention output pre-proj

// ---------------- K0: A1 = FacTu @ q_FacTs, A2 = FacTu @ v_FacTs ----------
__global__ void fact_small_kernel(const float* __restrict__ FacTu,
                                  const float* __restrict__ qF,
                                  const float* __restrict__ vF) {
    int idx = blockIdx.x * 256 + threadIdx.x;
    if (idx >= DIM * RANK * 2) return;
    int which = idx / (DIM * RANK);
    int rem = idx - which * (DIM * RANK);
    int i = rem / RANK, r = rem - (rem / RANK) * RANK;
    const float* F = which ? vF : qF;
    float s = 0.f;
#pragma unroll
    for (int k = 0; k < RANK; k++) s += FacTu[i * RANK + k] * F[k * RANK + r];
    (which ? g_A2 : g_A1)[i * RANK + r] = s;
}

// ---------------- K1: Weff = Wqkv + low-rank deltas on q/v slices ---------
__global__ void weff_kernel(const float* __restrict__ Wqkv,
                            const float* __restrict__ FacTv) {
    int idx = blockIdx.x * 256 + threadIdx.x;
    if (idx >= DIM * 3 * DIM) return;
    int i = idx / (3 * DIM);
    int j = idx - i * (3 * DIM);
    float w = Wqkv[idx];
    if (j < DIM) {
        float s = 0.f;
#pragma unroll
        for (int r = 0; r < RANK; r++) s += g_A1[i * RANK + r] * FacTv[r * DIM + j];
        w += FACT_S * s;
    } else if (j >= 2 * DIM) {
        int jj = j - 2 * DIM;
        float s = 0.f;
#pragma unroll
        for (int r = 0; r < RANK; r++) s += g_A2[i * RANK + r] * FacTv[r * DIM + jj];
        w += FACT_S * s;
    }
    g_Weff[idx] = w;
}

// ---------------- SGEMM 128x128x16, 256 threads, 8x8 per thread ----------
// C[M,N] = A[M,K] @ B[K,N] (+ bias[N]). M,N % 128 == 0, K % 16 == 0.
__global__ void __launch_bounds__(256, 2)
sgemm128(const float* __restrict__ A, const float* __restrict__ B,
         const float* __restrict__ bias, float* __restrict__ C,
         int M, int N, int K) {
    __shared__ float As[16 * 132];
    __shared__ float Bs[16 * 132];
    const int tid = threadIdx.x;
    const int tx = tid & 15, ty = tid >> 4;
    const int bm = blockIdx.y * 128, bn = blockIdx.x * 128;

    float acc[8][8];
#pragma unroll
    for (int i = 0; i < 8; i++)
#pragma unroll
        for (int j = 0; j < 8; j++) acc[i][j] = 0.f;

    for (int k0 = 0; k0 < K; k0 += 16) {
#pragma unroll
        for (int t = 0; t < 2; t++) {
            int idx = tid + t * 256;
            // A: 128 rows x 16 k, load float4 along k, store transposed
            int m = idx >> 2, kv = (idx & 3) * 4;
            float4 a = *(const float4*)&A[(size_t)(bm + m) * K + k0 + kv];
            As[(kv + 0) * 132 + m] = a.x;
            As[(kv + 1) * 132 + m] = a.y;
            As[(kv + 2) * 132 + m] = a.z;
            As[(kv + 3) * 132 + m] = a.w;
            // B: 16 rows x 128 cols, float4 along n
            int kk = idx >> 5, nv = (idx & 31) * 4;
            *(float4*)&Bs[kk * 132 + nv] =
                *(const float4*)&B[(size_t)(k0 + kk) * N + bn + nv];
        }
        __syncthreads();
#pragma unroll
        for (int kk = 0; kk < 16; kk++) {
            float4 a0 = *(const float4*)&As[kk * 132 + ty * 4];
            float4 a1 = *(const float4*)&As[kk * 132 + 64 + ty * 4];
            float4 b0 = *(const float4*)&Bs[kk * 132 + tx * 4];
            float4 b1 = *(const float4*)&Bs[kk * 132 + 64 + tx * 4];
            float ra[8] = {a0.x, a0.y, a0.z, a0.w, a1.x, a1.y, a1.z, a1.w};
            float rb[8] = {b0.x, b0.y, b0.z, b0.w, b1.x, b1.y, b1.z, b1.w};
#pragma unroll
            for (int i = 0; i < 8; i++)
#pragma unroll
                for (int j = 0; j < 8; j++) acc[i][j] += ra[i] * rb[j];
        }
        __syncthreads();
    }

#pragma unroll
    for (int ih = 0; ih < 2; ih++)
#pragma unroll
        for (int i = 0; i < 4; i++) {
            int m = bm + ih * 64 + ty * 4 + i;
#pragma unroll
            for (int jh = 0; jh < 2; jh++) {
                int n = bn + jh * 64 + tx * 4;
                float4 bv = bias ? *(const float4*)&bias[n]
                                 : make_float4(0.f, 0.f, 0.f, 0.f);
                float4 o;
                o.x = acc[ih * 4 + i][jh * 4 + 0] + bv.x;
                o.y = acc[ih * 4 + i][jh * 4 + 1] + bv.y;
                o.z = acc[ih * 4 + i][jh * 4 + 2] + bv.z;
                o.w = acc[ih * 4 + i][jh * 4 + 3] + bv.w;
                *(float4*)&C[(size_t)m * N + n] = o;
            }
        }
}

// ---------------- K3: rel bias tables --------------------------------------
// relh[head, t, hk] = sum_c q[head,t,c] * rel_pos_h[hq(t)-hk+47, c]
__global__ void rel_tab_kernel(const float* __restrict__ rph,
                               const float* __restrict__ rpw) {
    int t = blockIdx.x;           // 0..2303
    int hq = t / GH, wq = t - (t / GH) * GH;
    __shared__ float qv[DIM];
    __shared__ float Rhs[GH * HD];
    __shared__ float Rws[GH * HD];
    int tid = threadIdx.x;        // 256
    for (int i = tid; i < DIM; i += 256) qv[i] = g_qkv[(size_t)t * (3 * DIM) + i];
    for (int i = tid; i < GH * HD; i += 256) {
        int k = i >> 6, c = i & 63;
        Rhs[i] = rph[(hq - k + GH - 1) * HD + c];
        Rws[i] = rpw[(wq - k + GH - 1) * HD + c];
    }
    __syncthreads();
    for (int o = tid; o < NH * GH * 2; o += 256) {
        int which = o & 1;
        int rest = o >> 1;
        int head = rest / GH, k = rest - (rest / GH) * GH;
        const float* R = (which ? Rws : Rhs) + k * HD;
        const float* q = qv + head * HD;
        float s = 0.f;
#pragma unroll
        for (int c = 0; c < HD; c++) s += q[c] * R[c];
        (which ? g_relw : g_relh)[((size_t)head * HW + t) * GH + k] = s;
    }
}

// ---------------- K4: flash attention per (head, q-tile) -------------------
// grid (36, 12), 256 threads, dynamic smem
#define KT_STRIDE 68
__global__ void __launch_bounds__(256, 2) attn_kernel() {
    extern __shared__ float sm[];
    float* Qs = sm;                    // [64][64] (pre-scaled by QK_SCALE)
    float* Kt = Qs + 64 * 64;          // [64][68] c-major: Kt[c*68 + r]
    float* Vs = Kt + 64 * KT_STRIDE;   // [64][64]
    float* Ps = Vs + 64 * 64;          // [64][64]
    float* Rh = Ps + 64 * 64;          // [64][48]
    float* Rw = Rh + 64 * GH;          // [64][48]

    const int head = blockIdx.y;
    const int qt0 = blockIdx.x * 64;
    const int tid = threadIdx.x;
    const int tx = tid & 15, ty = tid >> 4;

    for (int i = tid; i < 64 * 64; i += 256) {
        int r = i >> 6, c = i & 63;
        Qs[i] = QK_SCALE * g_qkv[(size_t)(qt0 + r) * (3 * DIM) + head * HD + c];
    }
    for (int i = tid; i < 64 * GH; i += 256) {
        int r = i / GH, c = i - (i / GH) * GH;
        Rh[i] = g_relh[((size_t)head * HW + qt0 + r) * GH + c];
        Rw[i] = g_relw[((size_t)head * HW + qt0 + r) * GH + c];
    }

    float m_i[4], l_i[4], O[4][4];
#pragma unroll
    for (int i = 0; i < 4; i++) {
        m_i[i] = -1e30f; l_i[i] = 0.f;
#pragma unroll
        for (int j = 0; j < 4; j++) O[i][j] = 0.f;
    }

    for (int kt = 0; kt < HW / 64; kt++) {
        const int kt0 = kt * 64;
        __syncthreads();   // previous iter done with Kt/Vs/Ps; iter0: Qs/Rh ready
        for (int i = tid; i < 64 * 64; i += 256) {
            int r = i >> 6, c = i & 63;
            const float* src = &g_qkv[(size_t)(kt0 + r) * (3 * DIM) + head * HD + c];
            Kt[c * KT_STRIDE + r] = src[DIM];       // K
            Vs[i] = src[2 * DIM];                   // V
        }
        __syncthreads();

        // S = (scaled Q) @ K^T
        float S[4][4];
#pragma unroll
        for (int i = 0; i < 4; i++)
#pragma unroll
            for (int j = 0; j < 4; j++) S[i][j] = 0.f;
#pragma unroll 4
        for (int c = 0; c < 64; c++) {
            float4 rb = *(const float4*)&Kt[c * KT_STRIDE + tx * 4];
            float ra0 = Qs[(ty * 4 + 0) * 64 + c];
            float ra1 = Qs[(ty * 4 + 1) * 64 + c];
            float ra2 = Qs[(ty * 4 + 2) * 64 + c];
            float ra3 = Qs[(ty * 4 + 3) * 64 + c];
            S[0][0] += ra0 * rb.x; S[0][1] += ra0 * rb.y; S[0][2] += ra0 * rb.z; S[0][3] += ra0 * rb.w;
            S[1][0] += ra1 * rb.x; S[1][1] += ra1 * rb.y; S[1][2] += ra1 * rb.z; S[1][3] += ra1 * rb.w;
            S[2][0] += ra2 * rb.x; S[2][1] += ra2 * rb.y; S[2][2] += ra2 * rb.z; S[2][3] += ra2 * rb.w;
            S[3][0] += ra3 * rb.x; S[3][1] += ra3 * rb.y; S[3][2] += ra3 * rb.z; S[3][3] += ra3 * rb.w;
        }

        // add rel-pos bias
        int hk4[4], wk4[4];
#pragma unroll
        for (int j = 0; j < 4; j++) {
            int key = kt0 + tx * 4 + j;
            hk4[j] = key / GH;
            wk4[j] = key - hk4[j] * GH;
        }
#pragma unroll
        for (int i = 0; i < 4; i++) {
            const float* rh = &Rh[(ty * 4 + i) * GH];
            const float* rw = &Rw[(ty * 4 + i) * GH];
#pragma unroll
            for (int j = 0; j < 4; j++)
                S[i][j] += rh[hk4[j]] + rw[wk4[j]];
        }

        // online softmax update (row reduce over tx = lane bits 0..3)
#pragma unroll
        for (int i = 0; i < 4; i++) {
            float mloc = fmaxf(fmaxf(S[i][0], S[i][1]), fmaxf(S[i][2], S[i][3]));
#pragma unroll
            for (int off = 1; off < 16; off <<= 1)
                mloc = fmaxf(mloc, __shfl_xor_sync(0xffffffffu, mloc, off));
            float mnew = fmaxf(m_i[i], mloc);
            float alpha = __expf(m_i[i] - mnew);
            m_i[i] = mnew;
            float rs = 0.f;
#pragma unroll
            for (int j = 0; j < 4; j++) {
                float e = __expf(S[i][j] - mnew);
                S[i][j] = e;
                rs += e;
            }
#pragma unroll
            for (int off = 1; off < 16; off <<= 1)
                rs += __shfl_xor_sync(0xffffffffu, rs, off);
            l_i[i] = l_i[i] * alpha + rs;
#pragma unroll
            for (int j = 0; j < 4; j++) O[i][j] *= alpha;
        }

        // stage P, then O += P @ V
#pragma unroll
        for (int i = 0; i < 4; i++)
            *(float4*)&Ps[(ty * 4 + i) * 64 + tx * 4] =
                make_float4(S[i][0], S[i][1], S[i][2], S[i][3]);
        __syncthreads();
#pragma unroll 4
        for (int j = 0; j < 64; j++) {
            float4 vb = *(const float4*)&Vs[j * 64 + tx * 4];
            float p0 = Ps[(ty * 4 + 0) * 64 + j];
            float p1 = Ps[(ty * 4 + 1) * 64 + j];
            float p2 = Ps[(ty * 4 + 2) * 64 + j];
            float p3 = Ps[(ty * 4 + 3) * 64 + j];
            O[0][0] += p0 * vb.x; O[0][1] += p0 * vb.y; O[0][2] += p0 * vb.z; O[0][3] += p0 * vb.w;
            O[1][0] += p1 * vb.x; O[1][1] += p1 * vb.y; O[1][2] += p1 * vb.z; O[1][3] += p1 * vb.w;
            O[2][0] += p2 * vb.x; O[2][1] += p2 * vb.y; O[2][2] += p2 * vb.z; O[2][3] += p2 * vb.w;
            O[3][0] += p3 * vb.x; O[3][1] += p3 * vb.y; O[3][2] += p3 * vb.z; O[3][3] += p3 * vb.w;
        }
    }

    // epilogue: divide by l, write head-interleaved output
#pragma unroll
    for (int i = 0; i < 4; i++) {
        float inv = 1.f / l_i[i];
        int row = qt0 + ty * 4 + i;
        float4 o = make_float4(O[i][0] * inv, O[i][1] * inv, O[i][2] * inv, O[i][3] * inv);
        *(float4*)&g_opre[(size_t)row * DIM + head * HD + tx * 4] = o;
    }
}

#define ATTN_SMEM ((64*64 + 64*KT_STRIDE + 64*64 + 64*64 + 64*GH + 64*GH) * sizeof(float))

// ---------------- launch ---------------------------------------------------
extern "C" void kernel_launch(void* const* d_in, const int* in_sizes, int n_in,
                              void* d_out, int out_size) {
    const float* x     = (const float*)d_in[0];
    const float* Wqkv  = (const float*)d_in[1];
    const float* bqkv  = (const float*)d_in[2];
    const float* FacTu = (const float*)d_in[3];
    const float* FacTv = (const float*)d_in[4];
    const float* qF    = (const float*)d_in[5];
    const float* vF    = (const float*)d_in[6];
    const float* rph   = (const float*)d_in[7];
    const float* rpw   = (const float*)d_in[8];
    const float* Wproj = (const float*)d_in[9];
    const float* bproj = (const float*)d_in[10];
    float* out = (float*)d_out;

    void *pWeff, *pQkv, *pOpre;
    cudaGetSymbolAddress(&pWeff, g_Weff);
    cudaGetSymbolAddress(&pQkv, g_qkv);
    cudaGetSymbolAddress(&pOpre, g_opre);

    cudaFuncSetAttribute(attn_kernel,
                         cudaFuncAttributeMaxDynamicSharedMemorySize,
                         (int)ATTN_SMEM);

    // K0: tiny low-rank products
    fact_small_kernel<<<(DIM * RANK * 2 + 255) / 256, 256>>>(FacTu, qF, vF);

    // K1: fold low-rank deltas into qkv weight
    weff_kernel<<<(DIM * 3 * DIM + 255) / 256, 256>>>(Wqkv, FacTv);

    // K2: qkv = x @ Weff + bqkv   [2304, 2304]
    {
        dim3 grid((3 * DIM) / 128, HW / 128);
        sgemm128<<<grid, 256>>>(x, (const float*)pWeff, bqkv, (float*)pQkv,
                                HW, 3 * DIM, DIM);
    }

    // K3: rel-pos bias tables
    rel_tab_kernel<<<HW, 256>>>(rph, rpw);

    // K4: attention
    {
        dim3 grid(HW / 64, NH);
        attn_kernel<<<grid, 256, ATTN_SMEM>>>();
    }

    // K5: out = opre @ Wproj + bproj
    {
        dim3 grid(DIM / 128, HW / 128);
        sgemm128<<<grid, 256>>>((const float*)pOpre, Wproj, bproj, out,
                                HW, DIM, DIM);
    }
}

// round 2
// speedup vs baseline: 1.2054x; 1.2054x over previous
#include <cuda_runtime.h>

#define DIM   768
#define NH    12
#define HD    64
#define GH    48           // grid H = W
#define HW    2304         // 48*48
#define RANK  32
#define QK_SCALE 0.125f    // 64^-0.5
#define FACT_S 1.0f

typedef unsigned long long u64;

// ---------------- packed f32x2 helpers (sm_103a) ---------------------------
__device__ __forceinline__ u64 pack2f(float a, float b) {
    u64 r;
    asm("mov.b64 %0, {%1, %2};" : "=l"(r)
        : "r"(__float_as_uint(a)), "r"(__float_as_uint(b)));
    return r;
}
__device__ __forceinline__ void unpack2f(u64 v, float& a, float& b) {
    unsigned x, y;
    asm("mov.b64 {%0, %1}, %2;" : "=r"(x), "=r"(y) : "l"(v));
    a = __uint_as_float(x);
    b = __uint_as_float(y);
}
__device__ __forceinline__ void ffma2(u64& d, u64 a, u64 b) {
    asm("fma.rn.f32x2 %0, %1, %2, %0;" : "+l"(d) : "l"(a), "l"(b));
}
__device__ __forceinline__ u64 fmul2(u64 a, u64 b) {
    u64 d;
    asm("mul.rn.f32x2 %0, %1, %2;" : "=l"(d) : "l"(a), "l"(b));
    return d;
}

// ---------------- device scratch (no allocations allowed) ------------------
__device__ float g_A1[DIM * RANK];        // FacTu @ q_FacTs
__device__ float g_A2[DIM * RANK];        // FacTu @ v_FacTs
__device__ float g_Weff[DIM * 3 * DIM];   // folded qkv weight
__device__ float g_qkv[HW * 3 * DIM];     // qkv activations [2304, 2304]
__device__ float g_relh[NH * HW * GH];    // rel bias tables
__device__ float g_relw[NH * HW * GH];
__device__ float g_opre[HW * DIM];        // attention output pre-proj

// ---------------- K0: A1 = FacTu @ q_FacTs, A2 = FacTu @ v_FacTs -----------
__global__ void fact_small_kernel(const float* __restrict__ FacTu,
                                  const float* __restrict__ qF,
                                  const float* __restrict__ vF) {
    int idx = blockIdx.x * 256 + threadIdx.x;
    if (idx >= DIM * RANK * 2) return;
    int which = idx / (DIM * RANK);
    int rem = idx - which * (DIM * RANK);
    int i = rem / RANK, r = rem - (rem / RANK) * RANK;
    const float* F = which ? vF : qF;
    float s = 0.f;
#pragma unroll
    for (int k = 0; k < RANK; k++) s += FacTu[i * RANK + k] * F[k * RANK + r];
    (which ? g_A2 : g_A1)[i * RANK + r] = s;
}

// ---------------- K1: Weff = Wqkv + low-rank deltas on q/v slices ----------
__global__ void weff_kernel(const float* __restrict__ Wqkv,
                            const float* __restrict__ FacTv) {
    int idx = blockIdx.x * 256 + threadIdx.x;
    if (idx >= DIM * 3 * DIM) return;
    int i = idx / (3 * DIM);
    int j = idx - i * (3 * DIM);
    float w = Wqkv[idx];
    if (j < DIM) {
        float s = 0.f;
#pragma unroll
        for (int r = 0; r < RANK; r++) s += g_A1[i * RANK + r] * FacTv[r * DIM + j];
        w += FACT_S * s;
    } else if (j >= 2 * DIM) {
        int jj = j - 2 * DIM;
        float s = 0.f;
#pragma unroll
        for (int r = 0; r < RANK; r++) s += g_A2[i * RANK + r] * FacTv[r * DIM + jj];
        w += FACT_S * s;
    }
    g_Weff[idx] = w;
}

// ---------------- SGEMM 128x128x16, 256 threads, packed f32x2 --------------
// A tile stored with each value duplicated into a 64-bit lane pair, so the
// inner loop is pure LDS.128 + FFMA2 (no pack MOVs).
#define AS2_STRIDE 260
__global__ void __launch_bounds__(256, 2)
sgemm128(const float* __restrict__ A, const float* __restrict__ B,
         const float* __restrict__ bias, float* __restrict__ C,
         int M, int N, int K) {
    __shared__ float As2[16 * AS2_STRIDE];   // duplicated A: [k][m*2]
    __shared__ float Bs[16 * 132];
    const int tid = threadIdx.x;
    const int tx = tid & 15, ty = tid >> 4;
    const int bm = blockIdx.y * 128, bn = blockIdx.x * 128;

    u64 acc2[8][4];
#pragma unroll
    for (int i = 0; i < 8; i++)
#pragma unroll
        for (int j = 0; j < 4; j++) acc2[i][j] = 0ull;

    for (int k0 = 0; k0 < K; k0 += 16) {
#pragma unroll
        for (int t = 0; t < 2; t++) {
            int idx = tid + t * 256;
            // A: 128 rows x 16 k, load float4 along k, store dup-transposed
            int m = idx >> 2, kv = (idx & 3) * 4;
            float4 a = *(const float4*)&A[(size_t)(bm + m) * K + k0 + kv];
            *(u64*)&As2[(kv + 0) * AS2_STRIDE + m * 2] = pack2f(a.x, a.x);
            *(u64*)&As2[(kv + 1) * AS2_STRIDE + m * 2] = pack2f(a.y, a.y);
            *(u64*)&As2[(kv + 2) * AS2_STRIDE + m * 2] = pack2f(a.z, a.z);
            *(u64*)&As2[(kv + 3) * AS2_STRIDE + m * 2] = pack2f(a.w, a.w);
            // B: 16 rows x 128 cols, float4 along n
            int kk = idx >> 5, nv = (idx & 31) * 4;
            *(float4*)&Bs[kk * 132 + nv] =
                *(const float4*)&B[(size_t)(k0 + kk) * N + bn + nv];
        }
        __syncthreads();
#pragma unroll
        for (int kk = 0; kk < 16; kk++) {
            ulonglong2 aA = *(const ulonglong2*)&As2[kk * AS2_STRIDE + (ty * 4 + 0) * 2];
            ulonglong2 aB = *(const ulonglong2*)&As2[kk * AS2_STRIDE + (ty * 4 + 2) * 2];
            ulonglong2 aC = *(const ulonglong2*)&As2[kk * AS2_STRIDE + (64 + ty * 4 + 0) * 2];
            ulonglong2 aD = *(const ulonglong2*)&As2[kk * AS2_STRIDE + (64 + ty * 4 + 2) * 2];
            ulonglong2 b0 = *(const ulonglong2*)&Bs[kk * 132 + tx * 4];
            ulonglong2 b1 = *(const ulonglong2*)&Bs[kk * 132 + 64 + tx * 4];
            u64 ad[8] = {aA.x, aA.y, aB.x, aB.y, aC.x, aC.y, aD.x, aD.y};
#pragma unroll
            for (int i = 0; i < 8; i++) {
                ffma2(acc2[i][0], ad[i], b0.x);
                ffma2(acc2[i][1], ad[i], b0.y);
                ffma2(acc2[i][2], ad[i], b1.x);
                ffma2(acc2[i][3], ad[i], b1.y);
            }
        }
        __syncthreads();
    }

#pragma unroll
    for (int ih = 0; ih < 2; ih++)
#pragma unroll
        for (int i = 0; i < 4; i++) {
            int m = bm + ih * 64 + ty * 4 + i;
            int r = ih * 4 + i;
#pragma unroll
            for (int jh = 0; jh < 2; jh++) {
                int n = bn + jh * 64 + tx * 4;
                float4 bv = bias ? *(const float4*)&bias[n]
                                 : make_float4(0.f, 0.f, 0.f, 0.f);
                float c0, c1, c2, c3;
                unpack2f(acc2[r][jh * 2 + 0], c0, c1);
                unpack2f(acc2[r][jh * 2 + 1], c2, c3);
                float4 o = make_float4(c0 + bv.x, c1 + bv.y, c2 + bv.z, c3 + bv.w);
                *(float4*)&C[(size_t)m * N + n] = o;
            }
        }
}

// ---------------- K3: rel bias tables (one block per pos/head/table) -------
// which==0: relh[head, hq*48+w, k] = dot64(q[t], rel_pos_h[hq-k+47])
// which==1: relw[head, h*48+wq, k] = dot64(q[t], rel_pos_w[wq-k+47])
__global__ void __launch_bounds__(256) rel_tab2_kernel(const float* __restrict__ rph,
                                                       const float* __restrict__ rpw) {
    __shared__ float Qs[GH * 68];
    __shared__ float Rs[GH * 68];
    const int pos = blockIdx.x;     // hq or wq
    const int head = blockIdx.y;
    const int which = blockIdx.z;   // 0: h, 1: w
    const int tid = threadIdx.x;

    for (int i = tid; i < GH * HD; i += 256) {
        int r = i >> 6, c = i & 63;
        int t = which ? (r * GH + pos) : (pos * GH + r);
        Qs[r * 68 + c] = g_qkv[(size_t)t * (3 * DIM) + head * HD + c];
    }
    const float* rp = which ? rpw : rph;
    for (int i = tid; i < GH * HD; i += 256) {
        int k = i >> 6, c = i & 63;
        Rs[k * 68 + c] = rp[(pos - k + GH - 1) * HD + c];
    }
    __syncthreads();

    const int tx = tid & 15, ty = tid >> 4;   // 16x16, each does 3x3
    u64 acc[3][3];
#pragma unroll
    for (int i = 0; i < 3; i++)
#pragma unroll
        for (int j = 0; j < 3; j++) acc[i][j] = 0ull;

    for (int c = 0; c < HD; c += 4) {
        ulonglong2 q[3], r[3];
#pragma unroll
        for (int i = 0; i < 3; i++) q[i] = *(const ulonglong2*)&Qs[(ty * 3 + i) * 68 + c];
#pragma unroll
        for (int j = 0; j < 3; j++) r[j] = *(const ulonglong2*)&Rs[(tx * 3 + j) * 68 + c];
#pragma unroll
        for (int i = 0; i < 3; i++)
#pragma unroll
            for (int j = 0; j < 3; j++) {
                ffma2(acc[i][j], q[i].x, r[j].x);
                ffma2(acc[i][j], q[i].y, r[j].y);
            }
    }

    float* outp = which ? g_relw : g_relh;
#pragma unroll
    for (int i = 0; i < 3; i++) {
        int row = ty * 3 + i;
        int t = which ? (row * GH + pos) : (pos * GH + row);
#pragma unroll
        for (int j = 0; j < 3; j++) {
            float lo, hi;
            unpack2f(acc[i][j], lo, hi);
            outp[((size_t)head * HW + t) * GH + tx * 3 + j] = lo + hi;
        }
    }
}

// ---------------- K4: flash attention per (head, q-tile), packed f32x2 -----
#define KT_STRIDE 68
__global__ void __launch_bounds__(256, 2) attn_kernel() {
    extern __shared__ float sm[];
    float* Qs = sm;                    // [64][64] (pre-scaled by QK_SCALE)
    float* Kt = Qs + 64 * 64;          // [64][68] c-major: Kt[c*68 + r]
    float* Vs = Kt + 64 * KT_STRIDE;   // [64][64]
    float* Ps = Vs + 64 * 64;          // [64][64]
    float* Rh = Ps + 64 * 64;          // [64][48]
    float* Rw = Rh + 64 * GH;          // [64][48]

    const int head = blockIdx.y;
    const int qt0 = blockIdx.x * 64;
    const int tid = threadIdx.x;
    const int tx = tid & 15, ty = tid >> 4;

    for (int i = tid; i < 64 * 64; i += 256) {
        int r = i >> 6, c = i & 63;
        Qs[i] = QK_SCALE * g_qkv[(size_t)(qt0 + r) * (3 * DIM) + head * HD + c];
    }
    for (int i = tid; i < 64 * GH; i += 256) {
        int r = i / GH, c = i - (i / GH) * GH;
        Rh[i] = g_relh[((size_t)head * HW + qt0 + r) * GH + c];
        Rw[i] = g_relw[((size_t)head * HW + qt0 + r) * GH + c];
    }

    float m_i[4], l_i[4];
    u64 O2[4][2];
#pragma unroll
    for (int i = 0; i < 4; i++) {
        m_i[i] = -1e30f; l_i[i] = 0.f;
        O2[i][0] = 0ull; O2[i][1] = 0ull;
    }

    for (int kt = 0; kt < HW / 64; kt++) {
        const int kt0 = kt * 64;
        __syncthreads();
        for (int i = tid; i < 64 * 64; i += 256) {
            int r = i >> 6, c = i & 63;
            const float* src = &g_qkv[(size_t)(kt0 + r) * (3 * DIM) + head * HD + c];
            Kt[c * KT_STRIDE + r] = src[DIM];       // K
            Vs[i] = src[2 * DIM];                   // V
        }
        __syncthreads();

        // S = (scaled Q) @ K^T, packed along key columns
        u64 S2[4][2];
#pragma unroll
        for (int i = 0; i < 4; i++) { S2[i][0] = 0ull; S2[i][1] = 0ull; }

        for (int c = 0; c < 64; c += 4) {
            float qa[4][4];
#pragma unroll
            for (int i = 0; i < 4; i++) {
                float4 t4 = *(const float4*)&Qs[(ty * 4 + i) * 64 + c];
                qa[i][0] = t4.x; qa[i][1] = t4.y; qa[i][2] = t4.z; qa[i][3] = t4.w;
            }
#pragma unroll
            for (int cc = 0; cc < 4; cc++) {
                ulonglong2 kb = *(const ulonglong2*)&Kt[(c + cc) * KT_STRIDE + tx * 4];
#pragma unroll
                for (int i = 0; i < 4; i++) {
                    u64 ad = pack2f(qa[i][cc], qa[i][cc]);
                    ffma2(S2[i][0], ad, kb.x);
                    ffma2(S2[i][1], ad, kb.y);
                }
            }
        }

        float S[4][4];
#pragma unroll
        for (int i = 0; i < 4; i++) {
            unpack2f(S2[i][0], S[i][0], S[i][1]);
            unpack2f(S2[i][1], S[i][2], S[i][3]);
        }

        // add rel-pos bias
        int hk4[4], wk4[4];
#pragma unroll
        for (int j = 0; j < 4; j++) {
            int key = kt0 + tx * 4 + j;
            hk4[j] = key / GH;
            wk4[j] = key - hk4[j] * GH;
        }
#pragma unroll
        for (int i = 0; i < 4; i++) {
            const float* rh = &Rh[(ty * 4 + i) * GH];
            const float* rw = &Rw[(ty * 4 + i) * GH];
#pragma unroll
            for (int j = 0; j < 4; j++)
                S[i][j] += rh[hk4[j]] + rw[wk4[j]];
        }

        // online softmax update (row reduce over tx = lane bits 0..3)
#pragma unroll
        for (int i = 0; i < 4; i++) {
            float mloc = fmaxf(fmaxf(S[i][0], S[i][1]), fmaxf(S[i][2], S[i][3]));
#pragma unroll
            for (int off = 1; off < 16; off <<= 1)
                mloc = fmaxf(mloc, __shfl_xor_sync(0xffffffffu, mloc, off));
            float mnew = fmaxf(m_i[i], mloc);
            float alpha = __expf(m_i[i] - mnew);
            m_i[i] = mnew;
            float rs = 0.f;
#pragma unroll
            for (int j = 0; j < 4; j++) {
                float e = __expf(S[i][j] - mnew);
                S[i][j] = e;
                rs += e;
            }
#pragma unroll
            for (int off = 1; off < 16; off <<= 1)
                rs += __shfl_xor_sync(0xffffffffu, rs, off);
            l_i[i] = l_i[i] * alpha + rs;
            u64 av = pack2f(alpha, alpha);
            O2[i][0] = fmul2(O2[i][0], av);
            O2[i][1] = fmul2(O2[i][1], av);
        }

        // stage P, then O += P @ V
#pragma unroll
        for (int i = 0; i < 4; i++)
            *(float4*)&Ps[(ty * 4 + i) * 64 + tx * 4] =
                make_float4(S[i][0], S[i][1], S[i][2], S[i][3]);
        __syncthreads();

        for (int j = 0; j < 64; j += 4) {
            float pa[4][4];
#pragma unroll
            for (int i = 0; i < 4; i++) {
                float4 t4 = *(const float4*)&Ps[(ty * 4 + i) * 64 + j];
                pa[i][0] = t4.x; pa[i][1] = t4.y; pa[i][2] = t4.z; pa[i][3] = t4.w;
            }
#pragma unroll
            for (int jj = 0; jj < 4; jj++) {
                ulonglong2 vb = *(const ulonglong2*)&Vs[(j + jj) * 64 + tx * 4];
#pragma unroll
                for (int i = 0; i < 4; i++) {
                    u64 pd = pack2f(pa[i][jj], pa[i][jj]);
                    ffma2(O2[i][0], pd, vb.x);
                    ffma2(O2[i][1], pd, vb.y);
                }
            }
        }
    }

    // epilogue: divide by l, write head-interleaved output
#pragma unroll
    for (int i = 0; i < 4; i++) {
        float inv = 1.f / l_i[i];
        int row = qt0 + ty * 4 + i;
        float o0, o1, o2, o3;
        unpack2f(O2[i][0], o0, o1);
        unpack2f(O2[i][1], o2, o3);
        float4 o = make_float4(o0 * inv, o1 * inv, o2 * inv, o3 * inv);
        *(float4*)&g_opre[(size_t)row * DIM + head * HD + tx * 4] = o;
    }
}

#define ATTN_SMEM ((64*64 + 64*KT_STRIDE + 64*64 + 64*64 + 64*GH + 64*GH) * sizeof(float))

// ---------------- launch ----------------------------------------------------
extern "C" void kernel_launch(void* const* d_in, const int* in_sizes, int n_in,
                              void* d_out, int out_size) {
    const float* x     = (const float*)d_in[0];
    const float* Wqkv  = (const float*)d_in[1];
    const float* bqkv  = (const float*)d_in[2];
    const float* FacTu = (const float*)d_in[3];
    const float* FacTv = (const float*)d_in[4];
    const float* qF    = (const float*)d_in[5];
    const float* vF    = (const float*)d_in[6];
    const float* rph   = (const float*)d_in[7];
    const float* rpw   = (const float*)d_in[8];
    const float* Wproj = (const float*)d_in[9];
    const float* bproj = (const float*)d_in[10];
    float* out = (float*)d_out;

    void *pWeff, *pQkv, *pOpre;
    cudaGetSymbolAddress(&pWeff, g_Weff);
    cudaGetSymbolAddress(&pQkv, g_qkv);
    cudaGetSymbolAddress(&pOpre, g_opre);

    cudaFuncSetAttribute(attn_kernel,
                         cudaFuncAttributeMaxDynamicSharedMemorySize,
                         (int)ATTN_SMEM);

    // K0: tiny low-rank products
    fact_small_kernel<<<(DIM * RANK * 2 + 255) / 256, 256>>>(FacTu, qF, vF);

    // K1: fold low-rank deltas into qkv weight
    weff_kernel<<<(DIM * 3 * DIM + 255) / 256, 256>>>(Wqkv, FacTv);

    // K2: qkv = x @ Weff + bqkv   [2304, 2304]
    {
        dim3 grid((3 * DIM) / 128, HW / 128);
        sgemm128<<<grid, 256>>>(x, (const float*)pWeff, bqkv, (float*)pQkv,
                                HW, 3 * DIM, DIM);
    }

    // K3: rel-pos bias tables
    {
        dim3 grid(GH, NH, 2);
        rel_tab2_kernel<<<grid, 256>>>(rph, rpw);
    }

    // K4: attention
    {
        dim3 grid(HW / 64, NH);
        attn_kernel<<<grid, 256, ATTN_SMEM>>>();
    }

    // K5: out = opre @ Wproj + bproj
    {
        dim3 grid(DIM / 128, HW / 128);
        sgemm128<<<grid, 256>>>((const float*)pOpre, Wproj, bproj, out,
                                HW, DIM, DIM);
    }
}

// round 4
// speedup vs baseline: 1.6520x; 1.3706x over previous
#include <cuda_runtime.h>
#include <cuda_bf16.h>
#include <cstdint>

#define DIM   768
#define NH    12
#define HD    64
#define GH    48           // grid H = W
#define HW    2304         // 48*48
#define RANK  32
#define QK_SCALE 0.125f    // 64^-0.5
#define FACT_S 1.0f
#define NT    36           // kv tiles of 64

typedef unsigned long long u64;

// ---------------- packed f32x2 helpers --------------------------------------
__device__ __forceinline__ u64 pack2f(float a, float b) {
    u64 r;
    asm("mov.b64 %0, {%1, %2};" : "=l"(r)
        : "r"(__float_as_uint(a)), "r"(__float_as_uint(b)));
    return r;
}
__device__ __forceinline__ void unpack2f(u64 v, float& a, float& b) {
    unsigned x, y;
    asm("mov.b64 {%0, %1}, %2;" : "=r"(x), "=r"(y) : "l"(v));
    a = __uint_as_float(x);
    b = __uint_as_float(y);
}
__device__ __forceinline__ void ffma2(u64& d, u64 a, u64 b) {
    asm("fma.rn.f32x2 %0, %1, %2, %0;" : "+l"(d) : "l"(a), "l"(b));
}

// bf16x2 pack: low 16 bits = a, high = b
__device__ __forceinline__ uint32_t cvt_bf16x2(float a, float b) {
    uint32_t r;
    asm("cvt.rn.bf16x2.f32 %0, %1, %2;" : "=r"(r) : "f"(b), "f"(a));
    return r;
}
// split (a,b) into bf16x2 hi and lo remainder
__device__ __forceinline__ void split2(float a, float b, uint32_t& hi, uint32_t& lo) {
    uint32_t h = cvt_bf16x2(a, b);
    float ra = __uint_as_float(h << 16);
    float rb = __uint_as_float(h & 0xffff0000u);
    hi = h;
    lo = cvt_bf16x2(a - ra, b - rb);
}

// ---------------- mma / ldmatrix helpers ------------------------------------
__device__ __forceinline__ void mma16816(float c[4], const uint32_t a[4],
                                         uint32_t b0, uint32_t b1) {
    asm volatile(
        "mma.sync.aligned.m16n8k16.row.col.f32.bf16.bf16.f32 "
        "{%0,%1,%2,%3}, {%4,%5,%6,%7}, {%8,%9}, {%0,%1,%2,%3};"
        : "+f"(c[0]), "+f"(c[1]), "+f"(c[2]), "+f"(c[3])
        : "r"(a[0]), "r"(a[1]), "r"(a[2]), "r"(a[3]), "r"(b0), "r"(b1));
}
__device__ __forceinline__ void ldsm2(uint32_t& r0, uint32_t& r1, uint32_t addr) {
    asm volatile("ldmatrix.sync.aligned.m8n8.x2.shared.b16 {%0,%1}, [%2];"
                 : "=r"(r0), "=r"(r1) : "r"(addr));
}
__device__ __forceinline__ uint32_t smem_to_u32(const void* smem_ptr) {
    uint32_t addr;
    asm("{ .reg .u64 tmp; cvta.to.shared.u64 tmp, %1; cvt.u32.u64 %0, tmp; }"
        : "=r"(addr) : "l"(smem_ptr));
    return addr;
}

// ---------------- device scratch (no allocations allowed) ------------------
__device__ float g_A1[DIM * RANK];
__device__ float g_A2[DIM * RANK];
__device__ float g_Weff[DIM * 3 * DIM];
__device__ float g_qkv[HW * 3 * DIM];
__device__ float g_relh[NH * HW * GH];
__device__ float g_relw[NH * HW * GH];
__device__ float g_opre[HW * DIM];
// bf16 split K [head][key][dim] and transposed V [head][dim][key]
__device__ __nv_bfloat16 g_kh[NH * HW * HD];
__device__ __nv_bfloat16 g_kl[NH * HW * HD];
__device__ __nv_bfloat16 g_vh[NH * HD * HW];
__device__ __nv_bfloat16 g_vl[NH * HD * HW];

// ---------------- K0: A1 = FacTu @ q_FacTs, A2 = FacTu @ v_FacTs -----------
__global__ void fact_small_kernel(const float* __restrict__ FacTu,
                                  const float* __restrict__ qF,
                                  const float* __restrict__ vF) {
    int idx = blockIdx.x * 256 + threadIdx.x;
    if (idx >= DIM * RANK * 2) return;
    int which = idx / (DIM * RANK);
    int rem = idx - which * (DIM * RANK);
    int i = rem / RANK, r = rem - (rem / RANK) * RANK;
    const float* F = which ? vF : qF;
    float s = 0.f;
#pragma unroll
    for (int k = 0; k < RANK; k++) s += FacTu[i * RANK + k] * F[k * RANK + r];
    (which ? g_A2 : g_A1)[i * RANK + r] = s;
}

// ---------------- K1: Weff = Wqkv + low-rank deltas ------------------------
__global__ void weff_kernel(const float* __restrict__ Wqkv,
                            const float* __restrict__ FacTv) {
    int idx = blockIdx.x * 256 + threadIdx.x;
    if (idx >= DIM * 3 * DIM) return;
    int i = idx / (3 * DIM);
    int j = idx - i * (3 * DIM);
    float w = Wqkv[idx];
    if (j < DIM) {
        float s = 0.f;
#pragma unroll
        for (int r = 0; r < RANK; r++) s += g_A1[i * RANK + r] * FacTv[r * DIM + j];
        w += FACT_S * s;
    } else if (j >= 2 * DIM) {
        int jj = j - 2 * DIM;
        float s = 0.f;
#pragma unroll
        for (int r = 0; r < RANK; r++) s += g_A2[i * RANK + r] * FacTv[r * DIM + jj];
        w += FACT_S * s;
    }
    g_Weff[idx] = w;
}

// ---------------- SGEMM 128x128x16, packed f32x2 ---------------------------
#define AS2_STRIDE 260
__global__ void __launch_bounds__(256, 2)
sgemm128(const float* __restrict__ A, const float* __restrict__ B,
         const float* __restrict__ bias, float* __restrict__ C,
         int M, int N, int K) {
    __shared__ float As2[16 * AS2_STRIDE];
    __shared__ float Bs[16 * 132];
    const int tid = threadIdx.x;
    const int tx = tid & 15, ty = tid >> 4;
    const int bm = blockIdx.y * 128, bn = blockIdx.x * 128;

    u64 acc2[8][4];
#pragma unroll
    for (int i = 0; i < 8; i++)
#pragma unroll
        for (int j = 0; j < 4; j++) acc2[i][j] = 0ull;

    for (int k0 = 0; k0 < K; k0 += 16) {
#pragma unroll
        for (int t = 0; t < 2; t++) {
            int idx = tid + t * 256;
            int m = idx >> 2, kv = (idx & 3) * 4;
            float4 a = *(const float4*)&A[(size_t)(bm + m) * K + k0 + kv];
            *(u64*)&As2[(kv + 0) * AS2_STRIDE + m * 2] = pack2f(a.x, a.x);
            *(u64*)&As2[(kv + 1) * AS2_STRIDE + m * 2] = pack2f(a.y, a.y);
            *(u64*)&As2[(kv + 2) * AS2_STRIDE + m * 2] = pack2f(a.z, a.z);
            *(u64*)&As2[(kv + 3) * AS2_STRIDE + m * 2] = pack2f(a.w, a.w);
            int kk = idx >> 5, nv = (idx & 31) * 4;
            *(float4*)&Bs[kk * 132 + nv] =
                *(const float4*)&B[(size_t)(k0 + kk) * N + bn + nv];
        }
        __syncthreads();
#pragma unroll
        for (int kk = 0; kk < 16; kk++) {
            ulonglong2 aA = *(const ulonglong2*)&As2[kk * AS2_STRIDE + (ty * 4 + 0) * 2];
            ulonglong2 aB = *(const ulonglong2*)&As2[kk * AS2_STRIDE + (ty * 4 + 2) * 2];
            ulonglong2 aC = *(const ulonglong2*)&As2[kk * AS2_STRIDE + (64 + ty * 4 + 0) * 2];
            ulonglong2 aD = *(const ulonglong2*)&As2[kk * AS2_STRIDE + (64 + ty * 4 + 2) * 2];
            ulonglong2 b0 = *(const ulonglong2*)&Bs[kk * 132 + tx * 4];
            ulonglong2 b1 = *(const ulonglong2*)&Bs[kk * 132 + 64 + tx * 4];
            u64 ad[8] = {aA.x, aA.y, aB.x, aB.y, aC.x, aC.y, aD.x, aD.y};
#pragma unroll
            for (int i = 0; i < 8; i++) {
                ffma2(acc2[i][0], ad[i], b0.x);
                ffma2(acc2[i][1], ad[i], b0.y);
                ffma2(acc2[i][2], ad[i], b1.x);
                ffma2(acc2[i][3], ad[i], b1.y);
            }
        }
        __syncthreads();
    }

#pragma unroll
    for (int ih = 0; ih < 2; ih++)
#pragma unroll
        for (int i = 0; i < 4; i++) {
            int m = bm + ih * 64 + ty * 4 + i;
            int r = ih * 4 + i;
#pragma unroll
            for (int jh = 0; jh < 2; jh++) {
                int n = bn + jh * 64 + tx * 4;
                float4 bv = bias ? *(const float4*)&bias[n]
                                 : make_float4(0.f, 0.f, 0.f, 0.f);
                float c0, c1, c2, c3;
                unpack2f(acc2[r][jh * 2 + 0], c0, c1);
                unpack2f(acc2[r][jh * 2 + 1], c2, c3);
                float4 o = make_float4(c0 + bv.x, c1 + bv.y, c2 + bv.z, c3 + bv.w);
                *(float4*)&C[(size_t)m * N + n] = o;
            }
        }
}

// ---------------- K3: rel bias tables ---------------------------------------
__global__ void __launch_bounds__(256) rel_tab2_kernel(const float* __restrict__ rph,
                                                       const float* __restrict__ rpw) {
    __shared__ float Qs[GH * 68];
    __shared__ float Rs[GH * 68];
    const int pos = blockIdx.x;
    const int head = blockIdx.y;
    const int which = blockIdx.z;
    const int tid = threadIdx.x;

    for (int i = tid; i < GH * HD; i += 256) {
        int r = i >> 6, c = i & 63;
        int t = which ? (r * GH + pos) : (pos * GH + r);
        Qs[r * 68 + c] = g_qkv[(size_t)t * (3 * DIM) + head * HD + c];
    }
    const float* rp = which ? rpw : rph;
    for (int i = tid; i < GH * HD; i += 256) {
        int k = i >> 6, c = i & 63;
        Rs[k * 68 + c] = rp[(pos - k + GH - 1) * HD + c];
    }
    __syncthreads();

    const int tx = tid & 15, ty = tid >> 4;
    u64 acc[3][3];
#pragma unroll
    for (int i = 0; i < 3; i++)
#pragma unroll
        for (int j = 0; j < 3; j++) acc[i][j] = 0ull;

    for (int c = 0; c < HD; c += 4) {
        ulonglong2 q[3], r[3];
#pragma unroll
        for (int i = 0; i < 3; i++) q[i] = *(const ulonglong2*)&Qs[(ty * 3 + i) * 68 + c];
#pragma unroll
        for (int j = 0; j < 3; j++) r[j] = *(const ulonglong2*)&Rs[(tx * 3 + j) * 68 + c];
#pragma unroll
        for (int i = 0; i < 3; i++)
#pragma unroll
            for (int j = 0; j < 3; j++) {
                ffma2(acc[i][j], q[i].x, r[j].x);
                ffma2(acc[i][j], q[i].y, r[j].y);
            }
    }

    float* outp = which ? g_relw : g_relh;
#pragma unroll
    for (int i = 0; i < 3; i++) {
        int row = ty * 3 + i;
        int t = which ? (row * GH + pos) : (pos * GH + row);
#pragma unroll
        for (int j = 0; j < 3; j++) {
            float lo, hi;
            unpack2f(acc[i][j], lo, hi);
            outp[((size_t)head * HW + t) * GH + tx * 3 + j] = lo + hi;
        }
    }
}

// ---------------- K3b: split K and transposed V into bf16 hi/lo -------------
__global__ void __launch_bounds__(256) kv_prep_kernel() {
    __shared__ float vs[64 * 65];
    const int kt0 = blockIdx.x * 64;
    const int head = blockIdx.y;
    const int tid = threadIdx.x;

    for (int i = tid; i < 64 * 64; i += 256) {
        int r = i >> 6, c = i & 63;
        const float* src = &g_qkv[(size_t)(kt0 + r) * (3 * DIM) + head * HD + c];
        float kv = src[DIM];
        __nv_bfloat16 kh = __float2bfloat16(kv);
        size_t ko = ((size_t)head * HW + kt0 + r) * HD + c;
        g_kh[ko] = kh;
        g_kl[ko] = __float2bfloat16(kv - __bfloat162float(kh));
        vs[r * 65 + c] = src[2 * DIM];
    }
    __syncthreads();
    for (int i = tid; i < 64 * 64; i += 256) {
        int d = i >> 6, k = i & 63;
        float v = vs[k * 65 + d];
        __nv_bfloat16 vh = __float2bfloat16(v);
        size_t vo = ((size_t)head * HD + d) * HW + kt0 + k;
        g_vh[vo] = vh;
        g_vl[vo] = __float2bfloat16(v - __bfloat162float(vh));
    }
}

// ---------------- K4: mma.sync flash attention ------------------------------
// smem buffer layout (per KV tile): Khi[64][72] | Klo | Vthi[64][72] | Vtlo
#define ROWB   144            // 72 bf16 = 144 bytes per padded row
#define ARR_SZ (64 * ROWB)    // 9216
#define SB_KLO ARR_SZ
#define SB_V   (2 * ARR_SZ)
#define SB_VLO (3 * ARR_SZ)
#define BUF_SZ (4 * ARR_SZ)   // 36864
#define SM_RH  (2 * BUF_SZ)                 // 73728
#define SM_RW  (SM_RH + 128 * GH * 4)       // +24576
#define SM_TOT (SM_RW + 128 * GH * 4)       // 122880

__device__ __forceinline__ void copy_kv_tile(char* dstbuf, int head, int kt0) {
    const int tid = threadIdx.x;
    const uint4* kh = (const uint4*)(g_kh + ((size_t)head * HW + kt0) * HD);
    const uint4* kl = (const uint4*)(g_kl + ((size_t)head * HW + kt0) * HD);
#pragma unroll
    for (int it = 0; it < 2; it++) {
        int i = tid + it * 256;
        int r = i >> 3, c = i & 7;
        uint32_t d = r * ROWB + c * 16;
        *(uint4*)(dstbuf + d) = kh[i];
        *(uint4*)(dstbuf + SB_KLO + d) = kl[i];
    }
    const char* vhb = (const char*)(g_vh + (size_t)head * HD * HW + kt0);
    const char* vlb = (const char*)(g_vl + (size_t)head * HD * HW + kt0);
#pragma unroll
    for (int it = 0; it < 2; it++) {
        int i = tid + it * 256;
        int dr = i >> 3, c = i & 7;
        uint32_t d = dr * ROWB + c * 16;
        size_t go = (size_t)dr * (HW * 2) + c * 16;
        *(uint4*)(dstbuf + SB_V + d) = *(const uint4*)(vhb + go);
        *(uint4*)(dstbuf + SB_VLO + d) = *(const uint4*)(vlb + go);
    }
}

__global__ void __launch_bounds__(256) attn_mma_kernel() {
    extern __shared__ char smc[];
    const uint32_t smb = smem_to_u32(smc);
    const int tid = threadIdx.x, lane = tid & 31, warp = tid >> 5;
    const int gid = lane >> 2, tig = lane & 3;
    const int head = blockIdx.y;
    const int qt0 = blockIdx.x * 128;

    // rel-bias rows for this q-tile
    float* Rh = (float*)(smc + SM_RH);
    float* Rw = (float*)(smc + SM_RW);
    {
        const float4* sH = (const float4*)&g_relh[((size_t)head * HW + qt0) * GH];
        const float4* sW = (const float4*)&g_relw[((size_t)head * HW + qt0) * GH];
        float4* dH = (float4*)Rh;
        float4* dW = (float4*)Rw;
        for (int i = tid; i < 128 * GH / 4; i += 256) { dH[i] = sH[i]; dW[i] = sW[i]; }
    }

    // Q fragments (held in regs for all tiles), scaled then split
    uint32_t qhi[4][4], qlo[4][4];
    {
        const float* q0 = &g_qkv[(size_t)(qt0 + warp * 16 + gid) * (3 * DIM) + head * HD];
        const float* q1 = q0 + (size_t)8 * (3 * DIM);
#pragma unroll
        for (int s = 0; s < 4; s++) {
            int c = 16 * s + 2 * tig;
            float2 v;
            v = *(const float2*)&q0[c];
            split2(QK_SCALE * v.x, QK_SCALE * v.y, qhi[s][0], qlo[s][0]);
            v = *(const float2*)&q1[c];
            split2(QK_SCALE * v.x, QK_SCALE * v.y, qhi[s][1], qlo[s][1]);
            v = *(const float2*)&q0[c + 8];
            split2(QK_SCALE * v.x, QK_SCALE * v.y, qhi[s][2], qlo[s][2]);
            v = *(const float2*)&q1[c + 8];
            split2(QK_SCALE * v.x, QK_SCALE * v.y, qhi[s][3], qlo[s][3]);
        }
    }

    copy_kv_tile(smc, head, 0);
    __syncthreads();

    float Oacc[8][4];
#pragma unroll
    for (int j = 0; j < 8; j++)
#pragma unroll
        for (int i = 0; i < 4; i++) Oacc[j][i] = 0.f;
    float rs0 = 0.f, rs1 = 0.f;

    const float* rh0 = &Rh[(warp * 16 + gid) * GH];
    const float* rh1 = rh0 + 8 * GH;
    const float* rw0 = &Rw[(warp * 16 + gid) * GH];
    const float* rw1 = rw0 + 8 * GH;
    // ldmatrix lane offset: rows via lane&7, col-halves via lane&8
    const uint32_t lmoff = (uint32_t)((lane & 7) * ROWB + (lane & 8) * 2);

    for (int t = 0; t < NT; t++) {
        const int kt0 = t * 64;
        const uint32_t kb = smb + (uint32_t)(t & 1) * BUF_SZ;
        if (t + 1 < NT) copy_kv_tile(smc + ((t + 1) & 1) * BUF_SZ, head, kt0 + 64);

        // ---- S = Qs @ K^T (3-pass hi/lo) ----
        float Sacc[8][4];
#pragma unroll
        for (int j = 0; j < 8; j++)
#pragma unroll
            for (int i = 0; i < 4; i++) Sacc[j][i] = 0.f;

#pragma unroll
        for (int j = 0; j < 8; j++) {
            uint32_t base = kb + (uint32_t)j * (8 * ROWB) + lmoff;
#pragma unroll
            for (int s = 0; s < 4; s++) {
                uint32_t bh0, bh1, bl0, bl1;
                ldsm2(bh0, bh1, base + s * 32);
                ldsm2(bl0, bl1, base + SB_KLO + s * 32);
                mma16816(Sacc[j], qhi[s], bh0, bh1);
                mma16816(Sacc[j], qlo[s], bh0, bh1);
                mma16816(Sacc[j], qhi[s], bl0, bl1);
            }
        }

        // ---- bias + exp (no max shift; logits bounded) ----
#pragma unroll
        for (int j = 0; j < 8; j++) {
            int k0 = kt0 + 8 * j + 2 * tig;
            int hk0 = k0 / GH, wk0 = k0 - hk0 * GH;
            int k1 = k0 + 1;
            int hk1 = k1 / GH, wk1 = k1 - hk1 * GH;
            float e0 = __expf(Sacc[j][0] + rh0[hk0] + rw0[wk0]);
            float e1 = __expf(Sacc[j][1] + rh0[hk1] + rw0[wk1]);
            float e2 = __expf(Sacc[j][2] + rh1[hk0] + rw1[wk0]);
            float e3 = __expf(Sacc[j][3] + rh1[hk1] + rw1[wk1]);
            rs0 += e0 + e1;
            rs1 += e2 + e3;
            Sacc[j][0] = e0; Sacc[j][1] = e1; Sacc[j][2] = e2; Sacc[j][3] = e3;
        }

        // ---- repack P into A-fragments (register-local) ----
        uint32_t phi[4][4], plo[4][4];
#pragma unroll
        for (int s = 0; s < 4; s++) {
            split2(Sacc[2 * s][0],     Sacc[2 * s][1],     phi[s][0], plo[s][0]);
            split2(Sacc[2 * s][2],     Sacc[2 * s][3],     phi[s][1], plo[s][1]);
            split2(Sacc[2 * s + 1][0], Sacc[2 * s + 1][1], phi[s][2], plo[s][2]);
            split2(Sacc[2 * s + 1][2], Sacc[2 * s + 1][3], phi[s][3], plo[s][3]);
        }

        // ---- O += P @ V (3-pass hi/lo), V^T tiles in smem ----
#pragma unroll
        for (int j = 0; j < 8; j++) {
            uint32_t base = kb + SB_V + (uint32_t)j * (8 * ROWB) + lmoff;
#pragma unroll
            for (int s = 0; s < 4; s++) {
                uint32_t vh0, vh1, vl0, vl1;
                ldsm2(vh0, vh1, base + s * 32);
                ldsm2(vl0, vl1, base + ARR_SZ + s * 32);
                mma16816(Oacc[j], phi[s], vh0, vh1);
                mma16816(Oacc[j], plo[s], vh0, vh1);
                mma16816(Oacc[j], phi[s], vl0, vl1);
            }
        }
        __syncthreads();
    }

    // row-sum reduce across the 4 threads of each group
    rs0 += __shfl_xor_sync(0xffffffffu, rs0, 1);
    rs0 += __shfl_xor_sync(0xffffffffu, rs0, 2);
    rs1 += __shfl_xor_sync(0xffffffffu, rs1, 1);
    rs1 += __shfl_xor_sync(0xffffffffu, rs1, 2);
    const float inv0 = 1.f / rs0, inv1 = 1.f / rs1;

    float* o0 = &g_opre[(size_t)(qt0 + warp * 16 + gid) * DIM + head * HD];
    float* o1 = o0 + (size_t)8 * DIM;
#pragma unroll
    for (int j = 0; j < 8; j++) {
        int c = 8 * j + 2 * tig;
        *(float2*)&o0[c] = make_float2(Oacc[j][0] * inv0, Oacc[j][1] * inv0);
        *(float2*)&o1[c] = make_float2(Oacc[j][2] * inv1, Oacc[j][3] * inv1);
    }
}

// ---------------- launch -----------------------------------------------------
extern "C" void kernel_launch(void* const* d_in, const int* in_sizes, int n_in,
                              void* d_out, int out_size) {
    const float* x     = (const float*)d_in[0];
    const float* Wqkv  = (const float*)d_in[1];
    const float* bqkv  = (const float*)d_in[2];
    const float* FacTu = (const float*)d_in[3];
    const float* FacTv = (const float*)d_in[4];
    const float* qF    = (const float*)d_in[5];
    const float* vF    = (const float*)d_in[6];
    const float* rph   = (const float*)d_in[7];
    const float* rpw   = (const float*)d_in[8];
    const float* Wproj = (const float*)d_in[9];
    const float* bproj = (const float*)d_in[10];
    float* out = (float*)d_out;

    void *pWeff, *pQkv, *pOpre;
    cudaGetSymbolAddress(&pWeff, g_Weff);
    cudaGetSymbolAddress(&pQkv, g_qkv);
    cudaGetSymbolAddress(&pOpre, g_opre);

    cudaFuncSetAttribute(attn_mma_kernel,
                         cudaFuncAttributeMaxDynamicSharedMemorySize,
                         (int)SM_TOT);

    fact_small_kernel<<<(DIM * RANK * 2 + 255) / 256, 256>>>(FacTu, qF, vF);
    weff_kernel<<<(DIM * 3 * DIM + 255) / 256, 256>>>(Wqkv, FacTv);

    {   // qkv = x @ Weff + bqkv
        dim3 grid((3 * DIM) / 128, HW / 128);
        sgemm128<<<grid, 256>>>(x, (const float*)pWeff, bqkv, (float*)pQkv,
                                HW, 3 * DIM, DIM);
    }
    {   // rel-pos tables
        dim3 grid(GH, NH, 2);
        rel_tab2_kernel<<<grid, 256>>>(rph, rpw);
    }
    {   // bf16 split K / transposed V
        dim3 grid(HW / 64, NH);
        kv_prep_kernel<<<grid, 256>>>();
    }
    {   // tensor-core (mma.sync) attention
        dim3 grid(HW / 128, NH);
        attn_mma_kernel<<<grid, 256, SM_TOT>>>();
    }
    {   // out = opre @ Wproj + bproj
        dim3 grid(DIM / 128, HW / 128);
        sgemm128<<<grid, 256>>>((const float*)pOpre, Wproj, bproj, out,
                                HW, DIM, DIM);
    }
}

// round 5
// speedup vs baseline: 2.3757x; 1.4380x over previous
#include <cuda_runtime.h>
#include <cuda_bf16.h>
#include <cstdint>

#define DIM   768
#define NH    12
#define HD    64
#define GH    48           // grid H = W
#define HW    2304         // 48*48
#define RANK  32
#define QK_SCALE 0.125f    // 64^-0.5
#define FACT_S 1.0f
#define NT    36           // kv tiles of 64

typedef unsigned long long u64;

// ---------------- packed f32x2 helpers --------------------------------------
__device__ __forceinline__ u64 pack2f(float a, float b) {
    u64 r;
    asm("mov.b64 %0, {%1, %2};" : "=l"(r)
        : "r"(__float_as_uint(a)), "r"(__float_as_uint(b)));
    return r;
}
__device__ __forceinline__ void unpack2f(u64 v, float& a, float& b) {
    unsigned x, y;
    asm("mov.b64 {%0, %1}, %2;" : "=r"(x), "=r"(y) : "l"(v));
    a = __uint_as_float(x);
    b = __uint_as_float(y);
}
__device__ __forceinline__ void ffma2(u64& d, u64 a, u64 b) {
    asm("fma.rn.f32x2 %0, %1, %2, %0;" : "+l"(d) : "l"(a), "l"(b));
}

// bf16x2 pack: low 16 bits = a, high = b
__device__ __forceinline__ uint32_t cvt_bf16x2(float a, float b) {
    uint32_t r;
    asm("cvt.rn.bf16x2.f32 %0, %1, %2;" : "=r"(r) : "f"(b), "f"(a));
    return r;
}
// split (a,b) into bf16x2 hi and lo remainder
__device__ __forceinline__ void split2(float a, float b, uint32_t& hi, uint32_t& lo) {
    uint32_t h = cvt_bf16x2(a, b);
    float ra = __uint_as_float(h << 16);
    float rb = __uint_as_float(h & 0xffff0000u);
    hi = h;
    lo = cvt_bf16x2(a - ra, b - rb);
}

// ---------------- mma / ldmatrix helpers ------------------------------------
__device__ __forceinline__ void mma16816(float c[4], const uint32_t a[4],
                                         uint32_t b0, uint32_t b1) {
    asm volatile(
        "mma.sync.aligned.m16n8k16.row.col.f32.bf16.bf16.f32 "
        "{%0,%1,%2,%3}, {%4,%5,%6,%7}, {%8,%9}, {%0,%1,%2,%3};"
        : "+f"(c[0]), "+f"(c[1]), "+f"(c[2]), "+f"(c[3])
        : "r"(a[0]), "r"(a[1]), "r"(a[2]), "r"(a[3]), "r"(b0), "r"(b1));
}
__device__ __forceinline__ void ldsm2(uint32_t& r0, uint32_t& r1, uint32_t addr) {
    asm volatile("ldmatrix.sync.aligned.m8n8.x2.shared.b16 {%0,%1}, [%2];"
                 : "=r"(r0), "=r"(r1) : "r"(addr));
}
__device__ __forceinline__ void ldsm4(uint32_t r[4], uint32_t addr) {
    asm volatile("ldmatrix.sync.aligned.m8n8.x4.shared.b16 {%0,%1,%2,%3}, [%4];"
                 : "=r"(r[0]), "=r"(r[1]), "=r"(r[2]), "=r"(r[3]) : "r"(addr));
}
__device__ __forceinline__ uint32_t smem_to_u32(const void* smem_ptr) {
    uint32_t addr;
    asm("{ .reg .u64 tmp; cvta.to.shared.u64 tmp, %1; cvt.u32.u64 %0, tmp; }"
        : "=r"(addr) : "l"(smem_ptr));
    return addr;
}

// ---------------- device scratch (no allocations allowed) ------------------
__device__ float g_A1[DIM * RANK];
__device__ float g_A2[DIM * RANK];
__device__ float g_qkv[HW * 3 * DIM];
__device__ float g_relh[NH * HW * GH];
__device__ float g_relw[NH * HW * GH];
__device__ float g_opre[HW * DIM];
// pre-split transposed weights: [N][K] bf16 hi/lo
__device__ __nv_bfloat16 g_wqkvT_h[3 * DIM * DIM];
__device__ __nv_bfloat16 g_wqkvT_l[3 * DIM * DIM];
__device__ __nv_bfloat16 g_wprojT_h[DIM * DIM];
__device__ __nv_bfloat16 g_wprojT_l[DIM * DIM];
// bf16 split K [head][key][dim] and transposed V [head][dim][key]
__device__ __nv_bfloat16 g_kh[NH * HW * HD];
__device__ __nv_bfloat16 g_kl[NH * HW * HD];
__device__ __nv_bfloat16 g_vh[NH * HD * HW];
__device__ __nv_bfloat16 g_vl[NH * HD * HW];

// ---------------- K0: A1 = FacTu @ q_FacTs, A2 = FacTu @ v_FacTs -----------
__global__ void fact_small_kernel(const float* __restrict__ FacTu,
                                  const float* __restrict__ qF,
                                  const float* __restrict__ vF) {
    int idx = blockIdx.x * 256 + threadIdx.x;
    if (idx >= DIM * RANK * 2) return;
    int which = idx / (DIM * RANK);
    int rem = idx - which * (DIM * RANK);
    int i = rem / RANK, r = rem - (rem / RANK) * RANK;
    const float* F = which ? vF : qF;
    float s = 0.f;
#pragma unroll
    for (int k = 0; k < RANK; k++) s += FacTu[i * RANK + k] * F[k * RANK + r];
    (which ? g_A2 : g_A1)[i * RANK + r] = s;
}

// ---------------- K1: transpose + low-rank fold + bf16 split ---------------
// Input W [KI][NJ] (KI=768 rows). Output WT_h/l [NJ][KI] bf16.
// mode 1: add FacT delta on j<768 (A1) and j>=1536 (A2) columns.
__global__ void __launch_bounds__(256)
wsplit_kernel(const float* __restrict__ W, const float* __restrict__ FacTv,
              __nv_bfloat16* __restrict__ WTh, __nv_bfloat16* __restrict__ WTl,
              int NJ, int mode) {
    __shared__ float tile[32 * 33];
    const int tid = threadIdx.x;
    const int j0 = blockIdx.x * 32;
    const int i0 = blockIdx.y * 32;

    {
        const int j = tid & 31;
        const int ib = tid >> 5;
        const float* Aarr = nullptr;
        int jj = j0 + j;
        if (mode) {
            if (jj < DIM) Aarr = g_A1;
            else if (jj >= 2 * DIM) { Aarr = g_A2; jj -= 2 * DIM; }
        }
#pragma unroll
        for (int it = 0; it < 4; it++) {
            int il = ib + it * 8;
            int i = i0 + il;
            float w = W[(size_t)i * NJ + j0 + j];
            if (Aarr) {
                float s = 0.f;
#pragma unroll
                for (int r = 0; r < RANK; r++)
                    s += Aarr[i * RANK + r] * FacTv[r * DIM + jj];
                w += FACT_S * s;
            }
            tile[il * 33 + j] = w;
        }
    }
    __syncthreads();
    {
        const int i = tid & 31;
        const int jb = tid >> 5;
#pragma unroll
        for (int it = 0; it < 4; it++) {
            int jl = jb + it * 8;
            float v = tile[i * 33 + jl];
            __nv_bfloat16 h = __float2bfloat16(v);
            size_t o = (size_t)(j0 + jl) * DIM + i0 + i;
            WTh[o] = h;
            WTl[o] = __float2bfloat16(v - __bfloat162float(h));
        }
    }
}

// ---------------- K2: HMMA GEMM, C[M][N] = A[M][K] @ BT^T + bias ------------
// A fp32 row-major; BT pre-split bf16 [N][K]; 3-pass hi/lo. K % 32 == 0.
#define GS 40   // smem row stride in bf16 elements (80B)
__global__ void __launch_bounds__(256)
hgemm128(const float* __restrict__ A,
         const __nv_bfloat16* __restrict__ BTh,
         const __nv_bfloat16* __restrict__ BTl,
         const float* __restrict__ bias, float* __restrict__ C,
         int M, int N, int K) {
    __shared__ __align__(16) __nv_bfloat16 Ah[128 * GS];
    __shared__ __align__(16) __nv_bfloat16 Al[128 * GS];
    __shared__ __align__(16) __nv_bfloat16 Bh[128 * GS];
    __shared__ __align__(16) __nv_bfloat16 Bl[128 * GS];

    const int tid = threadIdx.x, lane = tid & 31, warp = tid >> 5;
    const int wm = (warp >> 2) * 64, wn = (warp & 3) * 32;
    const int bm = blockIdx.y * 128, bn = blockIdx.x * 128;

    const uint32_t sAh = smem_to_u32(Ah), sAl = smem_to_u32(Al);
    const uint32_t sBh = smem_to_u32(Bh), sBl = smem_to_u32(Bl);

    // fill-thread mapping
    const int am = tid >> 1, ac = tid & 1;           // A: 128 rows x 2 float4-pairs
    const int bnr = tid >> 1, bc = tid & 1;          // B: 128 rows x 2 uint4-pairs

    float4 pa[4];        // A prefetch: rows am, cols (ac*4 + t*8)*... see below
    uint4 pbh[2], pbl[2];

    // A: each thread loads 4 float4 covering row am, 32 floats = 8 float4:
    //    thread pair (ac) covers float4 idx {ac, ac+2, ac+4, ac+6}
#define LOAD_A(k0) do { \
        const float* ap = &A[(size_t)(bm + am) * K + (k0)]; \
        pa[0] = *(const float4*)&ap[(ac) * 4]; \
        pa[1] = *(const float4*)&ap[(ac + 2) * 4]; \
        pa[2] = *(const float4*)&ap[(ac + 4) * 4]; \
        pa[3] = *(const float4*)&ap[(ac + 6) * 4]; \
    } while (0)
#define LOAD_B(k0) do { \
        const char* bph = (const char*)&BTh[(size_t)(bn + bnr) * K + (k0)]; \
        const char* bpl = (const char*)&BTl[(size_t)(bn + bnr) * K + (k0)]; \
        pbh[0] = *(const uint4*)(bph + bc * 16); \
        pbh[1] = *(const uint4*)(bph + bc * 16 + 32); \
        pbl[0] = *(const uint4*)(bpl + bc * 16); \
        pbl[1] = *(const uint4*)(bpl + bc * 16 + 32); \
    } while (0)

    float acc[4][4][4];
#pragma unroll
    for (int a = 0; a < 4; a++)
#pragma unroll
        for (int b = 0; b < 4; b++)
#pragma unroll
            for (int c = 0; c < 4; c++) acc[a][b][c] = 0.f;

    LOAD_A(0);
    LOAD_B(0);

    // ldmatrix lane addresses
    const uint32_t aoff = (uint32_t)((lane & 15) * GS + ((lane >> 4) << 3)) * 2;
    const uint32_t boff = (uint32_t)(((lane & 7) + ((lane & 16) >> 1)) * GS + ((lane & 8))) * 2;

    const int NKT = K / 32;
    for (int kt = 0; kt < NKT; kt++) {
        // store prefetched tile to smem
#pragma unroll
        for (int t = 0; t < 4; t++) {
            uint32_t h01 = cvt_bf16x2(pa[t].x, pa[t].y);
            uint32_t h23 = cvt_bf16x2(pa[t].z, pa[t].w);
            uint32_t l01 = cvt_bf16x2(pa[t].x - __uint_as_float(h01 << 16),
                                      pa[t].y - __uint_as_float(h01 & 0xffff0000u));
            uint32_t l23 = cvt_bf16x2(pa[t].z - __uint_as_float(h23 << 16),
                                      pa[t].w - __uint_as_float(h23 & 0xffff0000u));
            int col = (ac + 2 * t) * 4;
            *(uint2*)&Ah[am * GS + col] = make_uint2(h01, h23);
            *(uint2*)&Al[am * GS + col] = make_uint2(l01, l23);
        }
        *(uint4*)&Bh[bnr * GS + bc * 8] = pbh[0];
        *(uint4*)&Bh[bnr * GS + bc * 8 + 16] = pbh[1];
        *(uint4*)&Bl[bnr * GS + bc * 8] = pbl[0];
        *(uint4*)&Bl[bnr * GS + bc * 8 + 16] = pbl[1];
        __syncthreads();

        if (kt + 1 < NKT) {
            LOAD_A((kt + 1) * 32);
            LOAD_B((kt + 1) * 32);
        }

#pragma unroll
        for (int ks = 0; ks < 2; ks++) {
            uint32_t ah[4][4], al[4][4];
#pragma unroll
            for (int mt = 0; mt < 4; mt++) {
                uint32_t off = (uint32_t)(wm + mt * 16) * (GS * 2) + (uint32_t)ks * 32 + aoff;
                ldsm4(ah[mt], sAh + off);
                ldsm4(al[mt], sAl + off);
            }
            uint32_t bh[2][4], bl[2][4];
#pragma unroll
            for (int nt = 0; nt < 2; nt++) {
                uint32_t off = (uint32_t)(wn + nt * 16) * (GS * 2) + (uint32_t)ks * 32 + boff;
                ldsm4(bh[nt], sBh + off);
                ldsm4(bl[nt], sBl + off);
            }
#pragma unroll
            for (int mt = 0; mt < 4; mt++)
#pragma unroll
                for (int nt = 0; nt < 4; nt++) {
                    uint32_t b0h = bh[nt >> 1][(nt & 1) * 2];
                    uint32_t b1h = bh[nt >> 1][(nt & 1) * 2 + 1];
                    uint32_t b0l = bl[nt >> 1][(nt & 1) * 2];
                    uint32_t b1l = bl[nt >> 1][(nt & 1) * 2 + 1];
                    mma16816(acc[mt][nt], ah[mt], b0h, b1h);
                    mma16816(acc[mt][nt], al[mt], b0h, b1h);
                    mma16816(acc[mt][nt], ah[mt], b0l, b1l);
                }
        }
        __syncthreads();
    }

    // epilogue
    const int gid = lane >> 2, tig = lane & 3;
#pragma unroll
    for (int mt = 0; mt < 4; mt++) {
        int m0 = bm + wm + mt * 16 + gid;
#pragma unroll
        for (int nt = 0; nt < 4; nt++) {
            int n0 = bn + wn + nt * 8 + 2 * tig;
            float bx = bias ? bias[n0] : 0.f;
            float by = bias ? bias[n0 + 1] : 0.f;
            *(float2*)&C[(size_t)m0 * N + n0] =
                make_float2(acc[mt][nt][0] + bx, acc[mt][nt][1] + by);
            *(float2*)&C[(size_t)(m0 + 8) * N + n0] =
                make_float2(acc[mt][nt][2] + bx, acc[mt][nt][3] + by);
        }
    }
}

// ---------------- K3: rel bias tables ---------------------------------------
__global__ void __launch_bounds__(256) rel_tab2_kernel(const float* __restrict__ rph,
                                                       const float* __restrict__ rpw) {
    __shared__ float Qs[GH * 68];
    __shared__ float Rs[GH * 68];
    const int pos = blockIdx.x;
    const int head = blockIdx.y;
    const int which = blockIdx.z;
    const int tid = threadIdx.x;

    for (int i = tid; i < GH * HD; i += 256) {
        int r = i >> 6, c = i & 63;
        int t = which ? (r * GH + pos) : (pos * GH + r);
        Qs[r * 68 + c] = g_qkv[(size_t)t * (3 * DIM) + head * HD + c];
    }
    const float* rp = which ? rpw : rph;
    for (int i = tid; i < GH * HD; i += 256) {
        int k = i >> 6, c = i & 63;
        Rs[k * 68 + c] = rp[(pos - k + GH - 1) * HD + c];
    }
    __syncthreads();

    const int tx = tid & 15, ty = tid >> 4;
    u64 acc[3][3];
#pragma unroll
    for (int i = 0; i < 3; i++)
#pragma unroll
        for (int j = 0; j < 3; j++) acc[i][j] = 0ull;

    for (int c = 0; c < HD; c += 4) {
        ulonglong2 q[3], r[3];
#pragma unroll
        for (int i = 0; i < 3; i++) q[i] = *(const ulonglong2*)&Qs[(ty * 3 + i) * 68 + c];
#pragma unroll
        for (int j = 0; j < 3; j++) r[j] = *(const ulonglong2*)&Rs[(tx * 3 + j) * 68 + c];
#pragma unroll
        for (int i = 0; i < 3; i++)
#pragma unroll
            for (int j = 0; j < 3; j++) {
                ffma2(acc[i][j], q[i].x, r[j].x);
                ffma2(acc[i][j], q[i].y, r[j].y);
            }
    }

    float* outp = which ? g_relw : g_relh;
#pragma unroll
    for (int i = 0; i < 3; i++) {
        int row = ty * 3 + i;
        int t = which ? (row * GH + pos) : (pos * GH + row);
#pragma unroll
        for (int j = 0; j < 3; j++) {
            float lo, hi;
            unpack2f(acc[i][j], lo, hi);
            outp[((size_t)head * HW + t) * GH + tx * 3 + j] = lo + hi;
        }
    }
}

// ---------------- K3b: split K and transposed V into bf16 hi/lo -------------
__global__ void __launch_bounds__(256) kv_prep_kernel() {
    __shared__ float vs[64 * 65];
    const int kt0 = blockIdx.x * 64;
    const int head = blockIdx.y;
    const int tid = threadIdx.x;

    for (int i = tid; i < 64 * 64; i += 256) {
        int r = i >> 6, c = i & 63;
        const float* src = &g_qkv[(size_t)(kt0 + r) * (3 * DIM) + head * HD + c];
        float kv = src[DIM];
        __nv_bfloat16 kh = __float2bfloat16(kv);
        size_t ko = ((size_t)head * HW + kt0 + r) * HD + c;
        g_kh[ko] = kh;
        g_kl[ko] = __float2bfloat16(kv - __bfloat162float(kh));
        vs[r * 65 + c] = src[2 * DIM];
    }
    __syncthreads();
    for (int i = tid; i < 64 * 64; i += 256) {
        int d = i >> 6, k = i & 63;
        float v = vs[k * 65 + d];
        __nv_bfloat16 vh = __float2bfloat16(v);
        size_t vo = ((size_t)head * HD + d) * HW + kt0 + k;
        g_vh[vo] = vh;
        g_vl[vo] = __float2bfloat16(v - __bfloat162float(vh));
    }
}

// ---------------- K4: mma.sync flash attention ------------------------------
#define ROWB   144            // 72 bf16 = 144 bytes per padded row
#define ARR_SZ (64 * ROWB)    // 9216
#define SB_KLO ARR_SZ
#define SB_V   (2 * ARR_SZ)
#define SB_VLO (3 * ARR_SZ)
#define BUF_SZ (4 * ARR_SZ)   // 36864
#define SM_RH  (2 * BUF_SZ)
#define SM_RW  (SM_RH + 128 * GH * 4)
#define SM_TOT (SM_RW + 128 * GH * 4)

__device__ __forceinline__ void copy_kv_tile(char* dstbuf, int head, int kt0) {
    const int tid = threadIdx.x;
    const uint4* kh = (const uint4*)(g_kh + ((size_t)head * HW + kt0) * HD);
    const uint4* kl = (const uint4*)(g_kl + ((size_t)head * HW + kt0) * HD);
#pragma unroll
    for (int it = 0; it < 2; it++) {
        int i = tid + it * 256;
        int r = i >> 3, c = i & 7;
        uint32_t d = r * ROWB + c * 16;
        *(uint4*)(dstbuf + d) = kh[i];
        *(uint4*)(dstbuf + SB_KLO + d) = kl[i];
    }
    const char* vhb = (const char*)(g_vh + (size_t)head * HD * HW + kt0);
    const char* vlb = (const char*)(g_vl + (size_t)head * HD * HW + kt0);
#pragma unroll
    for (int it = 0; it < 2; it++) {
        int i = tid + it * 256;
        int dr = i >> 3, c = i & 7;
        uint32_t d = dr * ROWB + c * 16;
        size_t go = (size_t)dr * (HW * 2) + c * 16;
        *(uint4*)(dstbuf + SB_V + d) = *(const uint4*)(vhb + go);
        *(uint4*)(dstbuf + SB_VLO + d) = *(const uint4*)(vlb + go);
    }
}

__global__ void __launch_bounds__(256) attn_mma_kernel() {
    extern __shared__ char smc[];
    const uint32_t smb = smem_to_u32(smc);
    const int tid = threadIdx.x, lane = tid & 31, warp = tid >> 5;
    const int gid = lane >> 2, tig = lane & 3;
    const int head = blockIdx.y;
    const int qt0 = blockIdx.x * 128;

    float* Rh = (float*)(smc + SM_RH);
    float* Rw = (float*)(smc + SM_RW);
    {
        const float4* sH = (const float4*)&g_relh[((size_t)head * HW + qt0) * GH];
        const float4* sW = (const float4*)&g_relw[((size_t)head * HW + qt0) * GH];
        float4* dH = (float4*)Rh;
        float4* dW = (float4*)Rw;
        for (int i = tid; i < 128 * GH / 4; i += 256) { dH[i] = sH[i]; dW[i] = sW[i]; }
    }

    uint32_t qhi[4][4], qlo[4][4];
    {
        const float* q0 = &g_qkv[(size_t)(qt0 + warp * 16 + gid) * (3 * DIM) + head * HD];
        const float* q1 = q0 + (size_t)8 * (3 * DIM);
#pragma unroll
        for (int s = 0; s < 4; s++) {
            int c = 16 * s + 2 * tig;
            float2 v;
            v = *(const float2*)&q0[c];
            split2(QK_SCALE * v.x, QK_SCALE * v.y, qhi[s][0], qlo[s][0]);
            v = *(const float2*)&q1[c];
            split2(QK_SCALE * v.x, QK_SCALE * v.y, qhi[s][1], qlo[s][1]);
            v = *(const float2*)&q0[c + 8];
            split2(QK_SCALE * v.x, QK_SCALE * v.y, qhi[s][2], qlo[s][2]);
            v = *(const float2*)&q1[c + 8];
            split2(QK_SCALE * v.x, QK_SCALE * v.y, qhi[s][3], qlo[s][3]);
        }
    }

    copy_kv_tile(smc, head, 0);
    __syncthreads();

    float Oacc[8][4];
#pragma unroll
    for (int j = 0; j < 8; j++)
#pragma unroll
        for (int i = 0; i < 4; i++) Oacc[j][i] = 0.f;
    float rs0 = 0.f, rs1 = 0.f;

    const float* rh0 = &Rh[(warp * 16 + gid) * GH];
    const float* rh1 = rh0 + 8 * GH;
    const float* rw0 = &Rw[(warp * 16 + gid) * GH];
    const float* rw1 = rw0 + 8 * GH;
    const uint32_t lmoff = (uint32_t)((lane & 7) * ROWB + (lane & 8) * 2);

    for (int t = 0; t < NT; t++) {
        const int kt0 = t * 64;
        const uint32_t kb = smb + (uint32_t)(t & 1) * BUF_SZ;
        if (t + 1 < NT) copy_kv_tile(smc + ((t + 1) & 1) * BUF_SZ, head, kt0 + 64);

        float Sacc[8][4];
#pragma unroll
        for (int j = 0; j < 8; j++)
#pragma unroll
            for (int i = 0; i < 4; i++) Sacc[j][i] = 0.f;

#pragma unroll
        for (int j = 0; j < 8; j++) {
            uint32_t base = kb + (uint32_t)j * (8 * ROWB) + lmoff;
#pragma unroll
            for (int s = 0; s < 4; s++) {
                uint32_t bh0, bh1, bl0, bl1;
                ldsm2(bh0, bh1, base + s * 32);
                ldsm2(bl0, bl1, base + SB_KLO + s * 32);
                mma16816(Sacc[j], qhi[s], bh0, bh1);
                mma16816(Sacc[j], qlo[s], bh0, bh1);
                mma16816(Sacc[j], qhi[s], bl0, bl1);
            }
        }

#pragma unroll
        for (int j = 0; j < 8; j++) {
            int k0 = kt0 + 8 * j + 2 * tig;
            int hk0 = k0 / GH, wk0 = k0 - hk0 * GH;
            int k1 = k0 + 1;
            int hk1 = k1 / GH, wk1 = k1 - hk1 * GH;
            float e0 = __expf(Sacc[j][0] + rh0[hk0] + rw0[wk0]);
            float e1 = __expf(Sacc[j][1] + rh0[hk1] + rw0[wk1]);
            float e2 = __expf(Sacc[j][2] + rh1[hk0] + rw1[wk0]);
            float e3 = __expf(Sacc[j][3] + rh1[hk1] + rw1[wk1]);
            rs0 += e0 + e1;
            rs1 += e2 + e3;
            Sacc[j][0] = e0; Sacc[j][1] = e1; Sacc[j][2] = e2; Sacc[j][3] = e3;
        }

        uint32_t phi[4][4], plo[4][4];
#pragma unroll
        for (int s = 0; s < 4; s++) {
            split2(Sacc[2 * s][0],     Sacc[2 * s][1],     phi[s][0], plo[s][0]);
            split2(Sacc[2 * s][2],     Sacc[2 * s][3],     phi[s][1], plo[s][1]);
            split2(Sacc[2 * s + 1][0], Sacc[2 * s + 1][1], phi[s][2], plo[s][2]);
            split2(Sacc[2 * s + 1][2], Sacc[2 * s + 1][3], phi[s][3], plo[s][3]);
        }

#pragma unroll
        for (int j = 0; j < 8; j++) {
            uint32_t base = kb + SB_V + (uint32_t)j * (8 * ROWB) + lmoff;
#pragma unroll
            for (int s = 0; s < 4; s++) {
                uint32_t vh0, vh1, vl0, vl1;
                ldsm2(vh0, vh1, base + s * 32);
                ldsm2(vl0, vl1, base + ARR_SZ + s * 32);
                mma16816(Oacc[j], phi[s], vh0, vh1);
                mma16816(Oacc[j], plo[s], vh0, vh1);
                mma16816(Oacc[j], phi[s], vl0, vl1);
            }
        }
        __syncthreads();
    }

    rs0 += __shfl_xor_sync(0xffffffffu, rs0, 1);
    rs0 += __shfl_xor_sync(0xffffffffu, rs0, 2);
    rs1 += __shfl_xor_sync(0xffffffffu, rs1, 1);
    rs1 += __shfl_xor_sync(0xffffffffu, rs1, 2);
    const float inv0 = 1.f / rs0, inv1 = 1.f / rs1;

    float* o0 = &g_opre[(size_t)(qt0 + warp * 16 + gid) * DIM + head * HD];
    float* o1 = o0 + (size_t)8 * DIM;
#pragma unroll
    for (int j = 0; j < 8; j++) {
        int c = 8 * j + 2 * tig;
        *(float2*)&o0[c] = make_float2(Oacc[j][0] * inv0, Oacc[j][1] * inv0);
        *(float2*)&o1[c] = make_float2(Oacc[j][2] * inv1, Oacc[j][3] * inv1);
    }
}

// ---------------- launch -----------------------------------------------------
extern "C" void kernel_launch(void* const* d_in, const int* in_sizes, int n_in,
                              void* d_out, int out_size) {
    const float* x     = (const float*)d_in[0];
    const float* Wqkv  = (const float*)d_in[1];
    const float* bqkv  = (const float*)d_in[2];
    const float* FacTu = (const float*)d_in[3];
    const float* FacTv = (const float*)d_in[4];
    const float* qF    = (const float*)d_in[5];
    const float* vF    = (const float*)d_in[6];
    const float* rph   = (const float*)d_in[7];
    const float* rpw   = (const float*)d_in[8];
    const float* Wproj = (const float*)d_in[9];
    const float* bproj = (const float*)d_in[10];
    float* out = (float*)d_out;

    void *pQkv, *pOpre, *pWqT_h, *pWqT_l, *pWpT_h, *pWpT_l;
    cudaGetSymbolAddress(&pQkv, g_qkv);
    cudaGetSymbolAddress(&pOpre, g_opre);
    cudaGetSymbolAddress(&pWqT_h, g_wqkvT_h);
    cudaGetSymbolAddress(&pWqT_l, g_wqkvT_l);
    cudaGetSymbolAddress(&pWpT_h, g_wprojT_h);
    cudaGetSymbolAddress(&pWpT_l, g_wprojT_l);

    cudaFuncSetAttribute(attn_mma_kernel,
                         cudaFuncAttributeMaxDynamicSharedMemorySize,
                         (int)SM_TOT);

    fact_small_kernel<<<(DIM * RANK * 2 + 255) / 256, 256>>>(FacTu, qF, vF);

    {   // Wqkv (+delta) -> transposed split
        dim3 grid((3 * DIM) / 32, DIM / 32);
        wsplit_kernel<<<grid, 256>>>(Wqkv, FacTv,
                                     (__nv_bfloat16*)pWqT_h, (__nv_bfloat16*)pWqT_l,
                                     3 * DIM, 1);
    }
    {   // Wproj -> transposed split
        dim3 grid(DIM / 32, DIM / 32);
        wsplit_kernel<<<grid, 256>>>(Wproj, FacTv,
                                     (__nv_bfloat16*)pWpT_h, (__nv_bfloat16*)pWpT_l,
                                     DIM, 0);
    }
    {   // qkv = x @ Weff + bqkv (HMMA)
        dim3 grid((3 * DIM) / 128, HW / 128);
        hgemm128<<<grid, 256>>>(x, (const __nv_bfloat16*)pWqT_h,
                                (const __nv_bfloat16*)pWqT_l, bqkv,
                                (float*)pQkv, HW, 3 * DIM, DIM);
    }
    {   // rel-pos tables
        dim3 grid(GH, NH, 2);
        rel_tab2_kernel<<<grid, 256>>>(rph, rpw);
    }
    {   // bf16 split K / transposed V
        dim3 grid(HW / 64, NH);
        kv_prep_kernel<<<grid, 256>>>();
    }
    {   // tensor-core attention
        dim3 grid(HW / 128, NH);
        attn_mma_kernel<<<grid, 256, SM_TOT>>>();
    }
    {   // out = opre @ Wproj + bproj (HMMA)
        dim3 grid(DIM / 128, HW / 128);
        hgemm128<<<grid, 256>>>((const float*)pOpre, (const __nv_bfloat16*)pWpT_h,
                                (const __nv_bfloat16*)pWpT_l, bproj,
                                out, HW, DIM, DIM);
    }
}

// round 6
// speedup vs baseline: 2.4782x; 1.0432x over previous
#include <cuda_runtime.h>
#include <cuda_bf16.h>
#include <cstdint>

#define DIM   768
#define NH    12
#define HD    64
#define GH    48           // grid H = W
#define HW    2304         // 48*48
#define RANK  32
#define QK_SCALE 0.125f    // 64^-0.5
#define FACT_S 1.0f
#define NT    36           // kv tiles of 64

typedef unsigned long long u64;

// ---------------- packed helpers --------------------------------------------
__device__ __forceinline__ u64 pack2f(float a, float b) {
    u64 r;
    asm("mov.b64 %0, {%1, %2};" : "=l"(r)
        : "r"(__float_as_uint(a)), "r"(__float_as_uint(b)));
    return r;
}
__device__ __forceinline__ void unpack2f(u64 v, float& a, float& b) {
    unsigned x, y;
    asm("mov.b64 {%0, %1}, %2;" : "=r"(x), "=r"(y) : "l"(v));
    a = __uint_as_float(x);
    b = __uint_as_float(y);
}
__device__ __forceinline__ void ffma2(u64& d, u64 a, u64 b) {
    asm("fma.rn.f32x2 %0, %1, %2, %0;" : "+l"(d) : "l"(a), "l"(b));
}
__device__ __forceinline__ uint32_t cvt_bf16x2(float a, float b) {
    uint32_t r;
    asm("cvt.rn.bf16x2.f32 %0, %1, %2;" : "=r"(r) : "f"(b), "f"(a));
    return r;
}
__device__ __forceinline__ void split2(float a, float b, uint32_t& hi, uint32_t& lo) {
    uint32_t h = cvt_bf16x2(a, b);
    float ra = __uint_as_float(h << 16);
    float rb = __uint_as_float(h & 0xffff0000u);
    hi = h;
    lo = cvt_bf16x2(a - ra, b - rb);
}

// ---------------- mma / ldmatrix / cp.async helpers --------------------------
__device__ __forceinline__ void mma16816(float c[4], const uint32_t a[4],
                                         uint32_t b0, uint32_t b1) {
    asm volatile(
        "mma.sync.aligned.m16n8k16.row.col.f32.bf16.bf16.f32 "
        "{%0,%1,%2,%3}, {%4,%5,%6,%7}, {%8,%9}, {%0,%1,%2,%3};"
        : "+f"(c[0]), "+f"(c[1]), "+f"(c[2]), "+f"(c[3])
        : "r"(a[0]), "r"(a[1]), "r"(a[2]), "r"(a[3]), "r"(b0), "r"(b1));
}
__device__ __forceinline__ void ldsm2(uint32_t& r0, uint32_t& r1, uint32_t addr) {
    asm volatile("ldmatrix.sync.aligned.m8n8.x2.shared.b16 {%0,%1}, [%2];"
                 : "=r"(r0), "=r"(r1) : "r"(addr));
}
__device__ __forceinline__ void ldsm4(uint32_t r[4], uint32_t addr) {
    asm volatile("ldmatrix.sync.aligned.m8n8.x4.shared.b16 {%0,%1,%2,%3}, [%4];"
                 : "=r"(r[0]), "=r"(r[1]), "=r"(r[2]), "=r"(r[3]) : "r"(addr));
}
__device__ __forceinline__ uint32_t smem_to_u32(const void* smem_ptr) {
    uint32_t addr;
    asm("{ .reg .u64 tmp; cvta.to.shared.u64 tmp, %1; cvt.u32.u64 %0, tmp; }"
        : "=r"(addr) : "l"(smem_ptr));
    return addr;
}
__device__ __forceinline__ void cp16(uint32_t dst, const void* src) {
    asm volatile("cp.async.cg.shared.global [%0], [%1], 16;"
                 :: "r"(dst), "l"(src));
}
#define CP_COMMIT() asm volatile("cp.async.commit_group;" ::: "memory")
#define CP_WAIT0()  asm volatile("cp.async.wait_group 0;" ::: "memory")

// ---------------- device scratch (no allocations allowed) ------------------
__device__ float g_A1[DIM * RANK];
__device__ float g_A2[DIM * RANK];
__device__ float g_qkv[HW * 3 * DIM];
__device__ float g_relh[NH * HW * GH];
__device__ float g_relw[NH * HW * GH];
// pre-split inputs / intermediates
__device__ __align__(16) __nv_bfloat16 g_xh[HW * DIM];
__device__ __align__(16) __nv_bfloat16 g_xl[HW * DIM];
__device__ __align__(16) __nv_bfloat16 g_oph[HW * DIM];
__device__ __align__(16) __nv_bfloat16 g_opl[HW * DIM];
// pre-split transposed weights: [N][K] bf16 hi/lo
__device__ __align__(16) __nv_bfloat16 g_wqkvT_h[3 * DIM * DIM];
__device__ __align__(16) __nv_bfloat16 g_wqkvT_l[3 * DIM * DIM];
__device__ __align__(16) __nv_bfloat16 g_wprojT_h[DIM * DIM];
__device__ __align__(16) __nv_bfloat16 g_wprojT_l[DIM * DIM];
// bf16 split K [head][key][dim] and transposed V [head][dim][key]
__device__ __align__(16) __nv_bfloat16 g_kh[NH * HW * HD];
__device__ __align__(16) __nv_bfloat16 g_kl[NH * HW * HD];
__device__ __align__(16) __nv_bfloat16 g_vh[NH * HD * HW];
__device__ __align__(16) __nv_bfloat16 g_vl[NH * HD * HW];

// ---------------- K0: A1 = FacTu @ q_FacTs, A2 = FacTu @ v_FacTs -----------
__global__ void fact_small_kernel(const float* __restrict__ FacTu,
                                  const float* __restrict__ qF,
                                  const float* __restrict__ vF) {
    int idx = blockIdx.x * 256 + threadIdx.x;
    if (idx >= DIM * RANK * 2) return;
    int which = idx / (DIM * RANK);
    int rem = idx - which * (DIM * RANK);
    int i = rem / RANK, r = rem - (rem / RANK) * RANK;
    const float* F = which ? vF : qF;
    float s = 0.f;
#pragma unroll
    for (int k = 0; k < RANK; k++) s += FacTu[i * RANK + k] * F[k * RANK + r];
    (which ? g_A2 : g_A1)[i * RANK + r] = s;
}

// ---------------- K0b: split x into bf16 hi/lo ------------------------------
__global__ void __launch_bounds__(256) xsplit_kernel(const float* __restrict__ x) {
    int idx = blockIdx.x * 256 + threadIdx.x;   // one float4 per thread
    if (idx >= HW * DIM / 4) return;
    float4 v = *(const float4*)&x[idx * 4];
    uint32_t h0, l0, h1, l1;
    split2(v.x, v.y, h0, l0);
    split2(v.z, v.w, h1, l1);
    *(uint2*)&g_xh[idx * 4] = make_uint2(h0, h1);
    *(uint2*)&g_xl[idx * 4] = make_uint2(l0, l1);
}

// ---------------- K1: transpose + low-rank fold + bf16 split ---------------
__global__ void __launch_bounds__(256)
wsplit_kernel(const float* __restrict__ W, const float* __restrict__ FacTv,
              __nv_bfloat16* __restrict__ WTh, __nv_bfloat16* __restrict__ WTl,
              int NJ, int mode) {
    __shared__ float tile[32 * 33];
    const int tid = threadIdx.x;
    const int j0 = blockIdx.x * 32;
    const int i0 = blockIdx.y * 32;

    {
        const int j = tid & 31;
        const int ib = tid >> 5;
        const float* Aarr = nullptr;
        int jj = j0 + j;
        if (mode) {
            if (jj < DIM) Aarr = g_A1;
            else if (jj >= 2 * DIM) { Aarr = g_A2; jj -= 2 * DIM; }
        }
#pragma unroll
        for (int it = 0; it < 4; it++) {
            int il = ib + it * 8;
            int i = i0 + il;
            float w = W[(size_t)i * NJ + j0 + j];
            if (Aarr) {
                float s = 0.f;
#pragma unroll
                for (int r = 0; r < RANK; r++)
                    s += Aarr[i * RANK + r] * FacTv[r * DIM + jj];
                w += FACT_S * s;
            }
            tile[il * 33 + j] = w;
        }
    }
    __syncthreads();
    {
        const int i = tid & 31;
        const int jb = tid >> 5;
#pragma unroll
        for (int it = 0; it < 4; it++) {
            int jl = jb + it * 8;
            float v = tile[i * 33 + jl];
            __nv_bfloat16 h = __float2bfloat16(v);
            size_t o = (size_t)(j0 + jl) * DIM + i0 + i;
            WTh[o] = h;
            WTl[o] = __float2bfloat16(v - __bfloat162float(h));
        }
    }
}

// ---------------- K2: HMMA GEMM (all-bf16, cp.async double buffer) ----------
// C[M][N] = Apair @ Bpair^T + bias.  A hi/lo [M][K], B hi/lo [N][K]. K%32==0.
#define GS 40                 // smem row stride in bf16 (80B)
#define GARR 10240            // bytes per smem array (128 rows * 80B)
#define GBUF 40960            // bytes per stage (4 arrays)
__global__ void __launch_bounds__(256)
hgemm_bf16(const __nv_bfloat16* __restrict__ Ah_,
           const __nv_bfloat16* __restrict__ Al_,
           const __nv_bfloat16* __restrict__ Bh_,
           const __nv_bfloat16* __restrict__ Bl_,
           const float* __restrict__ bias, float* __restrict__ C,
           int M, int N, int K) {
    extern __shared__ __align__(16) char gsm[];
    const uint32_t smb = smem_to_u32(gsm);
    const int tid = threadIdx.x, lane = tid & 31, warp = tid >> 5;
    const int wm = (warp >> 2) * 64, wn = (warp & 3) * 32;
    const int bm = blockIdx.y * 128, bn = blockIdx.x * 128;

    // per-thread fill mapping: 8 chunks; arr = t>>1 (compile-time per unroll)
#define GB_ISSUE(k0) do { \
        _Pragma("unroll") \
        for (int t = 0; t < 8; t++) { \
            int i = tid + t * 256; \
            int arr = i >> 9, j = i & 511; \
            int row = j >> 2, c = j & 3; \
            const __nv_bfloat16* gptr = (arr == 0) ? Ah_ : (arr == 1) ? Al_ \
                                        : (arr == 2) ? Bh_ : Bl_; \
            int grow = (arr < 2 ? bm : bn) + row; \
            const char* src = (const char*)&gptr[(size_t)grow * K + (k0)] + c * 16; \
            cp16(sb + arr * GARR + row * 80 + c * 16, src); \
        } \
        CP_COMMIT(); \
    } while (0)

    float acc[4][4][4];
#pragma unroll
    for (int a = 0; a < 4; a++)
#pragma unroll
        for (int b = 0; b < 4; b++)
#pragma unroll
            for (int c = 0; c < 4; c++) acc[a][b][c] = 0.f;

    {
        uint32_t sb = smb;
        GB_ISSUE(0);
    }

    const uint32_t aoff = (uint32_t)((lane & 15) * GS + ((lane >> 4) << 3)) * 2;
    const uint32_t boff = (uint32_t)(((lane & 7) + ((lane & 16) >> 1)) * GS + (lane & 8)) * 2;

    const int NKT = K / 32;
    for (int kt = 0; kt < NKT; kt++) {
        CP_WAIT0();
        __syncthreads();
        if (kt + 1 < NKT) {
            uint32_t sb = smb + (uint32_t)((kt + 1) & 1) * GBUF;
            GB_ISSUE((kt + 1) * 32);
        }
        const uint32_t cb = smb + (uint32_t)(kt & 1) * GBUF;
        const uint32_t sAh = cb, sAl = cb + GARR, sBh = cb + 2 * GARR, sBl = cb + 3 * GARR;

#pragma unroll
        for (int ks = 0; ks < 2; ks++) {
            uint32_t ah[4][4], al[4][4];
#pragma unroll
            for (int mt = 0; mt < 4; mt++) {
                uint32_t off = (uint32_t)(wm + mt * 16) * (GS * 2) + (uint32_t)ks * 32 + aoff;
                ldsm4(ah[mt], sAh + off);
                ldsm4(al[mt], sAl + off);
            }
            uint32_t bh[2][4], bl[2][4];
#pragma unroll
            for (int nt = 0; nt < 2; nt++) {
                uint32_t off = (uint32_t)(wn + nt * 16) * (GS * 2) + (uint32_t)ks * 32 + boff;
                ldsm4(bh[nt], sBh + off);
                ldsm4(bl[nt], sBl + off);
            }
#pragma unroll
            for (int mt = 0; mt < 4; mt++)
#pragma unroll
                for (int nt = 0; nt < 4; nt++) {
                    uint32_t b0h = bh[nt >> 1][(nt & 1) * 2];
                    uint32_t b1h = bh[nt >> 1][(nt & 1) * 2 + 1];
                    uint32_t b0l = bl[nt >> 1][(nt & 1) * 2];
                    uint32_t b1l = bl[nt >> 1][(nt & 1) * 2 + 1];
                    mma16816(acc[mt][nt], ah[mt], b0h, b1h);
                    mma16816(acc[mt][nt], al[mt], b0h, b1h);
                    mma16816(acc[mt][nt], ah[mt], b0l, b1l);
                }
        }
        __syncthreads();
    }

    const int gid = lane >> 2, tig = lane & 3;
#pragma unroll
    for (int mt = 0; mt < 4; mt++) {
        int m0 = bm + wm + mt * 16 + gid;
#pragma unroll
        for (int nt = 0; nt < 4; nt++) {
            int n0 = bn + wn + nt * 8 + 2 * tig;
            float bx = bias ? bias[n0] : 0.f;
            float by = bias ? bias[n0 + 1] : 0.f;
            *(float2*)&C[(size_t)m0 * N + n0] =
                make_float2(acc[mt][nt][0] + bx, acc[mt][nt][1] + by);
            *(float2*)&C[(size_t)(m0 + 8) * N + n0] =
                make_float2(acc[mt][nt][2] + bx, acc[mt][nt][3] + by);
        }
    }
}
#define HG_SMEM (2 * GBUF)

// ---------------- K3: rel bias tables ---------------------------------------
__global__ void __launch_bounds__(256) rel_tab2_kernel(const float* __restrict__ rph,
                                                       const float* __restrict__ rpw) {
    __shared__ float Qs[GH * 68];
    __shared__ float Rs[GH * 68];
    const int pos = blockIdx.x;
    const int head = blockIdx.y;
    const int which = blockIdx.z;
    const int tid = threadIdx.x;

    for (int i = tid; i < GH * HD; i += 256) {
        int r = i >> 6, c = i & 63;
        int t = which ? (r * GH + pos) : (pos * GH + r);
        Qs[r * 68 + c] = g_qkv[(size_t)t * (3 * DIM) + head * HD + c];
    }
    const float* rp = which ? rpw : rph;
    for (int i = tid; i < GH * HD; i += 256) {
        int k = i >> 6, c = i & 63;
        Rs[k * 68 + c] = rp[(pos - k + GH - 1) * HD + c];
    }
    __syncthreads();

    const int tx = tid & 15, ty = tid >> 4;
    u64 acc[3][3];
#pragma unroll
    for (int i = 0; i < 3; i++)
#pragma unroll
        for (int j = 0; j < 3; j++) acc[i][j] = 0ull;

    for (int c = 0; c < HD; c += 4) {
        ulonglong2 q[3], r[3];
#pragma unroll
        for (int i = 0; i < 3; i++) q[i] = *(const ulonglong2*)&Qs[(ty * 3 + i) * 68 + c];
#pragma unroll
        for (int j = 0; j < 3; j++) r[j] = *(const ulonglong2*)&Rs[(tx * 3 + j) * 68 + c];
#pragma unroll
        for (int i = 0; i < 3; i++)
#pragma unroll
            for (int j = 0; j < 3; j++) {
                ffma2(acc[i][j], q[i].x, r[j].x);
                ffma2(acc[i][j], q[i].y, r[j].y);
            }
    }

    float* outp = which ? g_relw : g_relh;
#pragma unroll
    for (int i = 0; i < 3; i++) {
        int row = ty * 3 + i;
        int t = which ? (row * GH + pos) : (pos * GH + row);
#pragma unroll
        for (int j = 0; j < 3; j++) {
            float lo, hi;
            unpack2f(acc[i][j], lo, hi);
            outp[((size_t)head * HW + t) * GH + tx * 3 + j] = lo + hi;
        }
    }
}

// ---------------- K3b: split K and transposed V into bf16 hi/lo -------------
__global__ void __launch_bounds__(256) kv_prep_kernel() {
    __shared__ float vs[64 * 65];
    const int kt0 = blockIdx.x * 64;
    const int head = blockIdx.y;
    const int tid = threadIdx.x;

    for (int i = tid; i < 64 * 64; i += 256) {
        int r = i >> 6, c = i & 63;
        const float* src = &g_qkv[(size_t)(kt0 + r) * (3 * DIM) + head * HD + c];
        float kv = src[DIM];
        __nv_bfloat16 kh = __float2bfloat16(kv);
        size_t ko = ((size_t)head * HW + kt0 + r) * HD + c;
        g_kh[ko] = kh;
        g_kl[ko] = __float2bfloat16(kv - __bfloat162float(kh));
        vs[r * 65 + c] = src[2 * DIM];
    }
    __syncthreads();
    for (int i = tid; i < 64 * 64; i += 256) {
        int d = i >> 6, k = i & 63;
        float v = vs[k * 65 + d];
        __nv_bfloat16 vh = __float2bfloat16(v);
        size_t vo = ((size_t)head * HD + d) * HW + kt0 + k;
        g_vh[vo] = vh;
        g_vl[vo] = __float2bfloat16(v - __bfloat162float(vh));
    }
}

// ---------------- K4: mma.sync flash attention (cp.async fills) -------------
#define ROWB   144            // 72 bf16 = 144 bytes per padded row
#define ARR_SZ (64 * ROWB)    // 9216
#define SB_KLO ARR_SZ
#define SB_V   (2 * ARR_SZ)
#define SB_VLO (3 * ARR_SZ)
#define BUF_SZ (4 * ARR_SZ)   // 36864
#define SM_RH  (2 * BUF_SZ)
#define SM_RW  (SM_RH + 128 * GH * 4)
#define SM_TOT (SM_RW + 128 * GH * 4)

__device__ __forceinline__ void copy_kv_async(uint32_t dstb, int head, int kt0) {
    const int tid = threadIdx.x;
    const char* khb = (const char*)(g_kh + ((size_t)head * HW + kt0) * HD);
    const char* klb = (const char*)(g_kl + ((size_t)head * HW + kt0) * HD);
#pragma unroll
    for (int it = 0; it < 2; it++) {
        int i = tid + it * 256;
        int r = i >> 3, c = i & 7;
        uint32_t d = r * ROWB + c * 16;
        cp16(dstb + d, khb + i * 16);
        cp16(dstb + SB_KLO + d, klb + i * 16);
    }
    const char* vhb = (const char*)(g_vh + (size_t)head * HD * HW + kt0);
    const char* vlb = (const char*)(g_vl + (size_t)head * HD * HW + kt0);
#pragma unroll
    for (int it = 0; it < 2; it++) {
        int i = tid + it * 256;
        int dr = i >> 3, c = i & 7;
        uint32_t d = dr * ROWB + c * 16;
        size_t go = (size_t)dr * (HW * 2) + c * 16;
        cp16(dstb + SB_V + d, vhb + go);
        cp16(dstb + SB_VLO + d, vlb + go);
    }
    CP_COMMIT();
}

__global__ void __launch_bounds__(256) attn_mma_kernel() {
    extern __shared__ char smc[];
    const uint32_t smb = smem_to_u32(smc);
    const int tid = threadIdx.x, lane = tid & 31, warp = tid >> 5;
    const int gid = lane >> 2, tig = lane & 3;
    const int head = blockIdx.y;
    const int qt0 = blockIdx.x * 128;

    copy_kv_async(smb, head, 0);

    float* Rh = (float*)(smc + SM_RH);
    float* Rw = (float*)(smc + SM_RW);
    {
        const float4* sH = (const float4*)&g_relh[((size_t)head * HW + qt0) * GH];
        const float4* sW = (const float4*)&g_relw[((size_t)head * HW + qt0) * GH];
        float4* dH = (float4*)Rh;
        float4* dW = (float4*)Rw;
        for (int i = tid; i < 128 * GH / 4; i += 256) { dH[i] = sH[i]; dW[i] = sW[i]; }
    }

    uint32_t qhi[4][4], qlo[4][4];
    {
        const float* q0 = &g_qkv[(size_t)(qt0 + warp * 16 + gid) * (3 * DIM) + head * HD];
        const float* q1 = q0 + (size_t)8 * (3 * DIM);
#pragma unroll
        for (int s = 0; s < 4; s++) {
            int c = 16 * s + 2 * tig;
            float2 v;
            v = *(const float2*)&q0[c];
            split2(QK_SCALE * v.x, QK_SCALE * v.y, qhi[s][0], qlo[s][0]);
            v = *(const float2*)&q1[c];
            split2(QK_SCALE * v.x, QK_SCALE * v.y, qhi[s][1], qlo[s][1]);
            v = *(const float2*)&q0[c + 8];
            split2(QK_SCALE * v.x, QK_SCALE * v.y, qhi[s][2], qlo[s][2]);
            v = *(const float2*)&q1[c + 8];
            split2(QK_SCALE * v.x, QK_SCALE * v.y, qhi[s][3], qlo[s][3]);
        }
    }

    CP_WAIT0();
    __syncthreads();

    float Oacc[8][4];
#pragma unroll
    for (int j = 0; j < 8; j++)
#pragma unroll
        for (int i = 0; i < 4; i++) Oacc[j][i] = 0.f;
    float rs0 = 0.f, rs1 = 0.f;

    const float* rh0 = &Rh[(warp * 16 + gid) * GH];
    const float* rh1 = rh0 + 8 * GH;
    const float* rw0 = &Rw[(warp * 16 + gid) * GH];
    const float* rw1 = rw0 + 8 * GH;
    const uint32_t lmoff = (uint32_t)((lane & 7) * ROWB + (lane & 8) * 2);

    for (int t = 0; t < NT; t++) {
        const int kt0 = t * 64;
        const uint32_t kb = smb + (uint32_t)(t & 1) * BUF_SZ;
        if (t + 1 < NT)
            copy_kv_async(smb + (uint32_t)((t + 1) & 1) * BUF_SZ, head, kt0 + 64);

        float Sacc[8][4];
#pragma unroll
        for (int j = 0; j < 8; j++)
#pragma unroll
            for (int i = 0; i < 4; i++) Sacc[j][i] = 0.f;

#pragma unroll
        for (int j = 0; j < 8; j++) {
            uint32_t base = kb + (uint32_t)j * (8 * ROWB) + lmoff;
#pragma unroll
            for (int s = 0; s < 4; s++) {
                uint32_t bh0, bh1, bl0, bl1;
                ldsm2(bh0, bh1, base + s * 32);
                ldsm2(bl0, bl1, base + SB_KLO + s * 32);
                mma16816(Sacc[j], qhi[s], bh0, bh1);
                mma16816(Sacc[j], qlo[s], bh0, bh1);
                mma16816(Sacc[j], qhi[s], bl0, bl1);
            }
        }

#pragma unroll
        for (int j = 0; j < 8; j++) {
            int k0 = kt0 + 8 * j + 2 * tig;
            int hk0 = k0 / GH, wk0 = k0 - hk0 * GH;
            int k1 = k0 + 1;
            int hk1 = k1 / GH, wk1 = k1 - hk1 * GH;
            float e0 = __expf(Sacc[j][0] + rh0[hk0] + rw0[wk0]);
            float e1 = __expf(Sacc[j][1] + rh0[hk1] + rw0[wk1]);
            float e2 = __expf(Sacc[j][2] + rh1[hk0] + rw1[wk0]);
            float e3 = __expf(Sacc[j][3] + rh1[hk1] + rw1[wk1]);
            rs0 += e0 + e1;
            rs1 += e2 + e3;
            Sacc[j][0] = e0; Sacc[j][1] = e1; Sacc[j][2] = e2; Sacc[j][3] = e3;
        }

        uint32_t phi[4][4], plo[4][4];
#pragma unroll
        for (int s = 0; s < 4; s++) {
            split2(Sacc[2 * s][0],     Sacc[2 * s][1],     phi[s][0], plo[s][0]);
            split2(Sacc[2 * s][2],     Sacc[2 * s][3],     phi[s][1], plo[s][1]);
            split2(Sacc[2 * s + 1][0], Sacc[2 * s + 1][1], phi[s][2], plo[s][2]);
            split2(Sacc[2 * s + 1][2], Sacc[2 * s + 1][3], phi[s][3], plo[s][3]);
        }

#pragma unroll
        for (int j = 0; j < 8; j++) {
            uint32_t base = kb + SB_V + (uint32_t)j * (8 * ROWB) + lmoff;
#pragma unroll
            for (int s = 0; s < 4; s++) {
                uint32_t vh0, vh1, vl0, vl1;
                ldsm2(vh0, vh1, base + s * 32);
                ldsm2(vl0, vl1, base + ARR_SZ + s * 32);
                mma16816(Oacc[j], phi[s], vh0, vh1);
                mma16816(Oacc[j], plo[s], vh0, vh1);
                mma16816(Oacc[j], phi[s], vl0, vl1);
            }
        }
        CP_WAIT0();
        __syncthreads();
    }

    rs0 += __shfl_xor_sync(0xffffffffu, rs0, 1);
    rs0 += __shfl_xor_sync(0xffffffffu, rs0, 2);
    rs1 += __shfl_xor_sync(0xffffffffu, rs1, 1);
    rs1 += __shfl_xor_sync(0xffffffffu, rs1, 2);
    const float inv0 = 1.f / rs0, inv1 = 1.f / rs1;

    const size_t r0 = (size_t)(qt0 + warp * 16 + gid) * DIM + head * HD;
    const size_t r1 = r0 + (size_t)8 * DIM;
#pragma unroll
    for (int j = 0; j < 8; j++) {
        int c = 8 * j + 2 * tig;
        uint32_t h, l;
        split2(Oacc[j][0] * inv0, Oacc[j][1] * inv0, h, l);
        *(uint32_t*)&g_oph[r0 + c] = h;
        *(uint32_t*)&g_opl[r0 + c] = l;
        split2(Oacc[j][2] * inv1, Oacc[j][3] * inv1, h, l);
        *(uint32_t*)&g_oph[r1 + c] = h;
        *(uint32_t*)&g_opl[r1 + c] = l;
    }
}

// ---------------- launch -----------------------------------------------------
extern "C" void kernel_launch(void* const* d_in, const int* in_sizes, int n_in,
                              void* d_out, int out_size) {
    const float* x     = (const float*)d_in[0];
    const float* Wqkv  = (const float*)d_in[1];
    const float* bqkv  = (const float*)d_in[2];
    const float* FacTu = (const float*)d_in[3];
    const float* FacTv = (const float*)d_in[4];
    const float* qF    = (const float*)d_in[5];
    const float* vF    = (const float*)d_in[6];
    const float* rph   = (const float*)d_in[7];
    const float* rpw   = (const float*)d_in[8];
    const float* Wproj = (const float*)d_in[9];
    const float* bproj = (const float*)d_in[10];
    float* out = (float*)d_out;

    void *pQkv, *pXh, *pXl, *pOph, *pOpl, *pWqT_h, *pWqT_l, *pWpT_h, *pWpT_l;
    cudaGetSymbolAddress(&pQkv, g_qkv);
    cudaGetSymbolAddress(&pXh, g_xh);
    cudaGetSymbolAddress(&pXl, g_xl);
    cudaGetSymbolAddress(&pOph, g_oph);
    cudaGetSymbolAddress(&pOpl, g_opl);
    cudaGetSymbolAddress(&pWqT_h, g_wqkvT_h);
    cudaGetSymbolAddress(&pWqT_l, g_wqkvT_l);
    cudaGetSymbolAddress(&pWpT_h, g_wprojT_h);
    cudaGetSymbolAddress(&pWpT_l, g_wprojT_l);

    cudaFuncSetAttribute(attn_mma_kernel,
                         cudaFuncAttributeMaxDynamicSharedMemorySize, (int)SM_TOT);
    cudaFuncSetAttribute(hgemm_bf16,
                         cudaFuncAttributeMaxDynamicSharedMemorySize, (int)HG_SMEM);

    fact_small_kernel<<<(DIM * RANK * 2 + 255) / 256, 256>>>(FacTu, qF, vF);
    xsplit_kernel<<<(HW * DIM / 4 + 255) / 256, 256>>>(x);

    {   // Wqkv (+delta) -> transposed split
        dim3 grid((3 * DIM) / 32, DIM / 32);
        wsplit_kernel<<<grid, 256>>>(Wqkv, FacTv,
                                     (__nv_bfloat16*)pWqT_h, (__nv_bfloat16*)pWqT_l,
                                     3 * DIM, 1);
    }
    {   // Wproj -> transposed split
        dim3 grid(DIM / 32, DIM / 32);
        wsplit_kernel<<<grid, 256>>>(Wproj, FacTv,
                                     (__nv_bfloat16*)pWpT_h, (__nv_bfloat16*)pWpT_l,
                                     DIM, 0);
    }
    {   // qkv = x @ Weff + bqkv (HMMA, all-bf16)
        dim3 grid((3 * DIM) / 128, HW / 128);
        hgemm_bf16<<<grid, 256, HG_SMEM>>>((const __nv_bfloat16*)pXh,
                                           (const __nv_bfloat16*)pXl,
                                           (const __nv_bfloat16*)pWqT_h,
                                           (const __nv_bfloat16*)pWqT_l,
                                           bqkv, (float*)pQkv, HW, 3 * DIM, DIM);
    }
    {   // rel-pos tables
        dim3 grid(GH, NH, 2);
        rel_tab2_kernel<<<grid, 256>>>(rph, rpw);
    }
    {   // bf16 split K / transposed V
        dim3 grid(HW / 64, NH);
        kv_prep_kernel<<<grid, 256>>>();
    }
    {   // tensor-core attention
        dim3 grid(HW / 128, NH);
        attn_mma_kernel<<<grid, 256, SM_TOT>>>();
    }
    {   // out = opre @ Wproj + bproj (HMMA, all-bf16)
        dim3 grid(DIM / 128, HW / 128);
        hgemm_bf16<<<grid, 256, HG_SMEM>>>((const __nv_bfloat16*)pOph,
                                           (const __nv_bfloat16*)pOpl,
                                           (const __nv_bfloat16*)pWpT_h,
                                           (const __nv_bfloat16*)pWpT_l,
                                           bproj, out, HW, DIM, DIM);
    }
}